// round 13
// baseline (speedup 1.0000x reference)
#include <cuda_runtime.h>
#include <cuda_fp16.h>
#include <math.h>
#include <stdint.h>

#define N_NODES 100000
#define FEAT    256
#define RANK    64
#define HIDD    512
#define OUTD    256
#define NEDGE   200000
#define KE      3
#define CSRCAP  12

// ---------------- scratch (device globals; no allocations allowed) ----------
__device__ __align__(16) float  g_emb_new[N_NODES * RANK];
__device__ __align__(16) __half g_hid_h[(size_t)N_NODES * HIDD];     // 102.4 MB
__device__ __align__(16) __half g_emb2_h[(size_t)N_NODES * OUTD];    // 51.2 MB
__device__ __align__(16) float  g_sum_c1[N_NODES * RANK];
__device__ __align__(16) float  g_sum_s[N_NODES * OUTD];
__device__ __align__(16) __half g_relu_s[(size_t)NEDGE * OUTD];      // 102.4 MB
__device__ __align__(16) __half g_emb_h[(size_t)N_NODES * FEAT];     // 51.2 MB
__device__ __align__(16) __half g_wp_h[RANK * FEAT];                 // [N][K]
__device__ __align__(16) __half g_w2a_h[HIDD * FEAT];
__device__ __align__(16) __half g_w2b_h[OUTD * HIDD];
__device__ __align__(16) float  g_wq_r[RANK * OUTD];                 // tf32 [K][N]
__device__ __align__(16) float  g_bias1[RANK];
__device__ __align__(16) float  g_bias2[HIDD];
__device__ int   g_csr[N_NODES * CSRCAP];
__device__ int   g_deg[N_NODES];
__device__ float g_dscale[N_NODES];
__device__ float g_invdeg[N_NODES];

__device__ __forceinline__ float tf32r(float x) {
    uint32_t r;
    asm("cvt.rna.tf32.f32 %0, %1;" : "=r"(r) : "f"(x));
    return __uint_as_float(r);
}
__device__ __forceinline__ uint32_t tf32u(float x) {
    uint32_t r;
    asm("cvt.rna.tf32.f32 %0, %1;" : "=r"(r) : "f"(x));
    return r;
}

// ---------------- utility kernels -------------------------------------------
__global__ void zero_kernel() {
    int i = blockIdx.x * blockDim.x + threadIdx.x;
    int stride = gridDim.x * blockDim.x;
    float4 z = make_float4(0.f, 0.f, 0.f, 0.f);
    float4* c4 = (float4*)g_sum_c1;
    for (int t = i; t < N_NODES * RANK / 4; t += stride) c4[t] = z;
    for (int t = i; t < N_NODES; t += stride) g_deg[t] = 0;
}

__global__ void csr_kernel(const int* __restrict__ en) {
    int i = blockIdx.x * blockDim.x + threadIdx.x;
    if (i < NEDGE * KE) {
        int v = en[i];
        int pos = atomicAdd(&g_deg[v], 1);
        if (pos < CSRCAP) g_csr[v * CSRCAP + pos] = i / KE;
    }
}

__global__ void scale_kernel() {
    int v = blockIdx.x * blockDim.x + threadIdx.x;
    if (v < N_NODES) {
        float d = (float)g_deg[v];
        g_dscale[v] = cbrtf(d);
        g_invdeg[v] = 1.0f / d;
    }
}

// emb (fp32) -> half
__global__ void emb_half_kernel(const float4* __restrict__ src, int n4) {
    int i = blockIdx.x * blockDim.x + threadIdx.x;
    if (i < n4) {
        float4 v = src[i];
        __half2 h0 = __float22half2_rn(make_float2(v.x, v.y));
        __half2 h1 = __float22half2_rn(make_float2(v.z, v.w));
        uint2 pk;
        pk.x = *(uint32_t*)&h0;
        pk.y = *(uint32_t*)&h1;
        ((uint2*)g_emb_h)[i] = pk;
    }
}

// weights: transpose to [N][K] half (G1/G2/G3), tf32-round wq, combine biases
__global__ void wprep_kernel(const float* __restrict__ Wp,  const float* __restrict__ bp,
                             const float* __restrict__ W2a, const float* __restrict__ b2a,
                             const float* __restrict__ W2b,
                             const float* __restrict__ Wq) {
    const int S1 = FEAT * RANK;
    const int S2 = S1 + FEAT * HIDD;
    const int S3 = S2 + HIDD * OUTD;
    const int S4 = S3 + RANK * OUTD;
    const int S5 = S4 + RANK;
    const int S6 = S5 + HIDD;
    int i = blockIdx.x * blockDim.x + threadIdx.x;
    if (i < S1) {
        int k = i / RANK, n = i % RANK;
        g_wp_h[n * FEAT + k] = __float2half_rn(Wp[i]);
    } else if (i < S2) {
        int j = i - S1;
        int k = j / HIDD, n = j % HIDD;
        g_w2a_h[n * FEAT + k] = __float2half_rn(W2a[j]);
    } else if (i < S3) {
        int j = i - S2;
        int k = j / OUTD, n = j % OUTD;
        g_w2b_h[n * HIDD + k] = __float2half_rn(W2b[j]);
    } else if (i < S4) {
        int j = i - S3;
        g_wq_r[j] = tf32r(Wq[j]);
    } else if (i < S5) {
        int j = i - S4;
        g_bias1[j] = Wp[FEAT * RANK + j] + bp[j];
    } else if (i < S6) {
        int j = i - S5;
        g_bias2[j] = W2a[FEAT * HIDD + j] + b2a[j];
    }
}

// ---------------- fp16 tensor-core GEMM (m16n8k16) ---------------------------
// A[M,K] half row-major, Bt[N,K] half (weights pre-transposed). BK=32, warp
// tile 64x32 (4x4 of m16n8k16), double-buffered cp.async (round-8 pipeline).
// C = act(A@B + bias); OUTHALF selects half or float output.
template <int WMW, int WNW, int TPB, bool RELU, bool OUTHALF>
__global__ __launch_bounds__(TPB) void gemm_h(
    int M, int N, int K,
    const __half* __restrict__ A, const __half* __restrict__ Bt,
    const float* __restrict__ bias, void* __restrict__ Cv)
{
    constexpr int BM = WMW * 64, BN = WNW * 32, BK = 32;
    constexpr int AST = 40;                 // halves; banks (20r+c)%32 distinct
    constexpr int BST = 40;
    constexpr int ATILE = BM * AST;         // halves
    constexpr int BTILE = BN * BST;
    constexpr int CA = BM * 4 / TPB;        // 16B chunks per thread
    constexpr int CB = BN * 4 / TPB;
    static_assert(CA >= 1 && CB >= 1, "tile/thread mismatch");
    static_assert(WMW * WNW * 32 == TPB, "warp layout mismatch");

    extern __shared__ __half smemh[];
    __half* AsB = smemh;
    __half* BsB = smemh + 2 * ATILE;

    int tid = threadIdx.x;
    int warp = tid >> 5, lane = tid & 31;
    int wm = warp / WNW, wn = warp % WNW;
    int lr = lane >> 2, lc = lane & 3;
    int block_m = blockIdx.y * BM, block_n = blockIdx.x * BN;

    float acc[4][4][4];
#pragma unroll
    for (int a = 0; a < 4; a++)
#pragma unroll
        for (int b = 0; b < 4; b++)
#pragma unroll
            for (int c = 0; c < 4; c++) acc[a][b][c] = 0.0f;

    auto load_tiles = [&](int it, __half* As, __half* Bs) {
#pragma unroll
        for (int i = 0; i < CA; i++) {
            int f = tid + TPB * i;
            int m = f >> 2, q = f & 3;                 // 4 x 16B per 32-half row
            int gr = block_m + m;
            uint32_t dst = (uint32_t)__cvta_generic_to_shared(As + m * AST + 8 * q);
            const __half* src = A + (size_t)gr * K + it * BK + 8 * q;
            int sz = (gr < M) ? 16 : 0;
            asm volatile("cp.async.cg.shared.global [%0], [%1], 16, %2;"
                         :: "r"(dst), "l"(src), "r"(sz));
        }
#pragma unroll
        for (int i = 0; i < CB; i++) {
            int f = tid + TPB * i;
            int n = f >> 2, q = f & 3;
            uint32_t dst = (uint32_t)__cvta_generic_to_shared(Bs + n * BST + 8 * q);
            const __half* src = Bt + (size_t)(block_n + n) * K + it * BK + 8 * q;
            asm volatile("cp.async.cg.shared.global [%0], [%1], 16;"
                         :: "r"(dst), "l"(src));
        }
        asm volatile("cp.async.commit_group;");
    };

    int nIter = K / BK;
    load_tiles(0, AsB, BsB);

    for (int it = 0; it < nIter; ++it) {
        int buf = it & 1;
        if (it + 1 < nIter) {
            load_tiles(it + 1, AsB + (buf ^ 1) * ATILE, BsB + (buf ^ 1) * BTILE);
            asm volatile("cp.async.wait_group 1;");
        } else {
            asm volatile("cp.async.wait_group 0;");
        }
        __syncthreads();
        const uint32_t* Au = (const uint32_t*)(AsB + buf * ATILE);   // 20 u32/row
        const uint32_t* Bu = (const uint32_t*)(BsB + buf * BTILE);

#pragma unroll
        for (int ks = 0; ks < 2; ks++) {                  // two k16 steps per BK=32
            uint32_t af[4][4], bf[4][2];
#pragma unroll
            for (int mt = 0; mt < 4; mt++) {
                int row = wm * 64 + mt * 16 + lr;
                int base = row * 20 + ks * 8 + lc;
                af[mt][0] = Au[base];                     // (row,   k0..k0+1)
                af[mt][1] = Au[base + 160];               // (row+8, k0..k0+1)
                af[mt][2] = Au[base + 4];                 // (row,   k0+8..9)
                af[mt][3] = Au[base + 164];               // (row+8, k0+8..9)
            }
#pragma unroll
            for (int nt = 0; nt < 4; nt++) {
                int n = wn * 32 + nt * 8 + lr;
                int base = n * 20 + ks * 8 + lc;
                bf[nt][0] = Bu[base];
                bf[nt][1] = Bu[base + 4];
            }
#pragma unroll
            for (int mt = 0; mt < 4; mt++)
#pragma unroll
                for (int nt = 0; nt < 4; nt++)
                    asm volatile(
                        "mma.sync.aligned.m16n8k16.row.col.f32.f16.f16.f32 "
                        "{%0,%1,%2,%3}, {%4,%5,%6,%7}, {%8,%9}, {%0,%1,%2,%3};"
                        : "+f"(acc[mt][nt][0]), "+f"(acc[mt][nt][1]),
                          "+f"(acc[mt][nt][2]), "+f"(acc[mt][nt][3])
                        : "r"(af[mt][0]), "r"(af[mt][1]), "r"(af[mt][2]), "r"(af[mt][3]),
                          "r"(bf[nt][0]), "r"(bf[nt][1]));
        }
        __syncthreads();
    }

    // epilogue
#pragma unroll
    for (int mt = 0; mt < 4; mt++) {
#pragma unroll
        for (int half_i = 0; half_i < 2; half_i++) {
            int row = block_m + wm * 64 + mt * 16 + lr + half_i * 8;
            if (row >= M) continue;
#pragma unroll
            for (int nt = 0; nt < 4; nt++) {
                int gc = block_n + wn * 32 + nt * 8 + 2 * lc;
                float v0 = acc[mt][nt][half_i * 2 + 0] + bias[gc];
                float v1 = acc[mt][nt][half_i * 2 + 1] + bias[gc + 1];
                if (RELU) { v0 = fmaxf(v0, 0.0f); v1 = fmaxf(v1, 0.0f); }
                if (OUTHALF) {
                    __half2 h = __float22half2_rn(make_float2(v0, v1));
                    *(__half2*)((__half*)Cv + (size_t)row * N + gc) = h;
                } else {
                    *(float2*)((float*)Cv + (size_t)row * N + gc) = make_float2(v0, v1);
                }
            }
        }
    }
}

constexpr size_t smem_h(int WMW, int WNW) {
    return (size_t)(2 * (WMW * 64) * 40 + 2 * (WNW * 32) * 40) * 2;
}

// ---------------- TF32 GEMM (G4 only: A=sum_c1 fp32, CVTA in-loop) -----------
template <int WMW, int WNW, int TPB, bool RELU>
__global__ __launch_bounds__(TPB) void gemm_v2(
    int M, int N, int K,
    const float* __restrict__ A, const float* __restrict__ B,
    const float* __restrict__ bias,
    const float* __restrict__ D, const float* __restrict__ rowscale,
    float* __restrict__ C)
{
    constexpr int BM = WMW * 64, BN = WNW * 32, BK = 32;
    constexpr int AST = BK + 4;
    constexpr int BST = BN + 8;
    constexpr int ATILE = BM * AST;
    constexpr int BTILE = BK * BST;
    constexpr int CA = BM * BK / (4 * TPB);
    constexpr int CB = BK * BN / (4 * TPB);
    static_assert(CA >= 1 && CB >= 1, "tile/thread mismatch");
    static_assert(WMW * WNW * 32 == TPB, "warp layout mismatch");

    extern __shared__ float smem[];
    float* AsB = smem;
    float* BsB = smem + 2 * ATILE;

    int tid = threadIdx.x;
    int warp = tid >> 5, lane = tid & 31;
    int wm = warp / WNW, wn = warp % WNW;
    int lr = lane >> 2, lc = lane & 3;
    int block_m = blockIdx.y * BM, block_n = blockIdx.x * BN;

    float acc[4][4][4];
#pragma unroll
    for (int a = 0; a < 4; a++)
#pragma unroll
        for (int b = 0; b < 4; b++)
#pragma unroll
            for (int c = 0; c < 4; c++) acc[a][b][c] = 0.0f;

    auto load_tiles = [&](int it, float* As, float* Bs) {
#pragma unroll
        for (int i = 0; i < CA; i++) {
            int f = tid + TPB * i;
            int m = f >> 3, q = f & 7;
            int gr = block_m + m;
            uint32_t dst = (uint32_t)__cvta_generic_to_shared(As + m * AST + 4 * q);
            const float* src = A + (size_t)gr * K + it * BK + 4 * q;
            int sz = (gr < M) ? 16 : 0;
            asm volatile("cp.async.cg.shared.global [%0], [%1], 16, %2;"
                         :: "r"(dst), "l"(src), "r"(sz));
        }
#pragma unroll
        for (int i = 0; i < CB; i++) {
            int f = tid + TPB * i;
            int n4 = f % (BN / 4), k = f / (BN / 4);
            uint32_t dst = (uint32_t)__cvta_generic_to_shared(Bs + k * BST + 4 * n4);
            const float* src = B + (size_t)(it * BK + k) * N + block_n + 4 * n4;
            asm volatile("cp.async.cg.shared.global [%0], [%1], 16;"
                         :: "r"(dst), "l"(src));
        }
        asm volatile("cp.async.commit_group;");
    };

    int nIter = K / BK;
    load_tiles(0, AsB, BsB);

    for (int it = 0; it < nIter; ++it) {
        int buf = it & 1;
        if (it + 1 < nIter) {
            load_tiles(it + 1, AsB + (buf ^ 1) * ATILE, BsB + (buf ^ 1) * BTILE);
            asm volatile("cp.async.wait_group 1;");
        } else {
            asm volatile("cp.async.wait_group 0;");
        }
        __syncthreads();
        const float* As = AsB + buf * ATILE;
        const float* Bs = BsB + buf * BTILE;

#pragma unroll
        for (int ks = 0; ks < 4; ks++) {
            int col = ks * 8 + lc;
            uint32_t af[4][4], bfr[4][2];
#pragma unroll
            for (int mt = 0; mt < 4; mt++) {
                const float* ap = As + (wm * 64 + mt * 16 + lr) * AST + col;
                af[mt][0] = tf32u(ap[0]);
                af[mt][1] = tf32u(ap[8 * AST]);
                af[mt][2] = tf32u(ap[4]);
                af[mt][3] = tf32u(ap[8 * AST + 4]);
            }
#pragma unroll
            for (int nt = 0; nt < 4; nt++) {
                const float* bp = Bs + col * BST + wn * 32 + nt * 8 + lr;
                bfr[nt][0] = __float_as_uint(bp[0]);
                bfr[nt][1] = __float_as_uint(bp[4 * BST]);
            }
#pragma unroll
            for (int mt = 0; mt < 4; mt++)
#pragma unroll
                for (int nt = 0; nt < 4; nt++)
                    asm volatile(
                        "mma.sync.aligned.m16n8k8.row.col.f32.tf32.tf32.f32 "
                        "{%0,%1,%2,%3}, {%4,%5,%6,%7}, {%8,%9}, {%0,%1,%2,%3};"
                        : "+f"(acc[mt][nt][0]), "+f"(acc[mt][nt][1]),
                          "+f"(acc[mt][nt][2]), "+f"(acc[mt][nt][3])
                        : "r"(af[mt][0]), "r"(af[mt][1]), "r"(af[mt][2]), "r"(af[mt][3]),
                          "r"(bfr[nt][0]), "r"(bfr[nt][1]));
        }
        __syncthreads();
    }

#pragma unroll
    for (int mt = 0; mt < 4; mt++) {
#pragma unroll
        for (int half_i = 0; half_i < 2; half_i++) {
            int row = block_m + wm * 64 + mt * 16 + lr + half_i * 8;
            if (row >= M) continue;
            float rs = rowscale[row];
#pragma unroll
            for (int nt = 0; nt < 4; nt++) {
                int gc = block_n + wn * 32 + nt * 8 + 2 * lc;
                float v0 = acc[mt][nt][half_i * 2 + 0];
                float v1 = acc[mt][nt][half_i * 2 + 1];
                float2 d = *(const float2*)(D + (size_t)row * N + gc);
                v0 += d.x; v1 += d.y;
                v0 = rs * v0 + bias[gc];
                v1 = rs * v1 + bias[gc + 1];
                if (RELU) { v0 = fmaxf(v0, 0.0f); v1 = fmaxf(v1, 0.0f); }
                *(float2*)(C + (size_t)row * N + gc) = make_float2(v0, v1);
            }
        }
    }
}

constexpr size_t smem_bytes(int WMW, int WNW) {
    return (size_t)(2 * (WMW * 64) * 36 + 2 * 32 * (WNW * 32 + 8)) * 4;
}

// ---------------- edge kernel (c1 atomics + relu_s fp16 store) ---------------
__device__ __forceinline__ void red4(float* p, float4 v) {
    asm volatile("red.global.add.v4.f32 [%0], {%1,%2,%3,%4};"
                 :: "l"(p), "f"(v.x), "f"(v.y), "f"(v.z), "f"(v.w) : "memory");
}
__device__ __forceinline__ float2 h2f(uint32_t u) {
    return __half22float2(*(__half2*)&u);
}
__device__ __forceinline__ uint32_t f2h(float a, float b) {
    __half2 h = __float22half2_rn(make_float2(a, b));
    return *(uint32_t*)&h;
}

__global__ __launch_bounds__(256) void edge_kernel(const int* __restrict__ en) {
    int wg = (blockIdx.x * blockDim.x + threadIdx.x) >> 5;
    int lane = threadIdx.x & 31;
    if (wg >= NEDGE) return;
    int v0 = en[wg * 3 + 0];
    int v1 = en[wg * 3 + 1];
    int v2 = en[wg * 3 + 2];
    float d0 = g_dscale[v0], d1 = g_dscale[v1], d2 = g_dscale[v2];

    if (lane < 16) {
        float4 a = *(const float4*)(g_emb_new + (size_t)v0 * RANK + lane * 4);
        float4 b = *(const float4*)(g_emb_new + (size_t)v1 * RANK + lane * 4);
        float4 c = *(const float4*)(g_emb_new + (size_t)v2 * RANK + lane * 4);
        a.x *= d0; a.y *= d0; a.z *= d0; a.w *= d0;
        b.x *= d1; b.y *= d1; b.z *= d1; b.w *= d1;
        c.x *= d2; c.y *= d2; c.z *= d2; c.w *= d2;
        float h0 = 0.5f * d0, h1 = 0.5f * d1, h2 = 0.5f * d2;
        float4 o0 = make_float4(h0 * b.x * c.x, h0 * b.y * c.y, h0 * b.z * c.z, h0 * b.w * c.w);
        float4 o1 = make_float4(h1 * a.x * c.x, h1 * a.y * c.y, h1 * a.z * c.z, h1 * a.w * c.w);
        float4 o2 = make_float4(h2 * a.x * b.x, h2 * a.y * b.y, h2 * a.z * b.z, h2 * a.w * b.w);
        red4(g_sum_c1 + (size_t)v0 * RANK + lane * 4, o0);
        red4(g_sum_c1 + (size_t)v1 * RANK + lane * 4, o1);
        red4(g_sum_c1 + (size_t)v2 * RANK + lane * 4, o2);
    }

    // emb2 is fp16: 256 halves/row = 32 uint4; one uint4 (8 halves) per lane
    const uint4* e0 = (const uint4*)(g_emb2_h + (size_t)v0 * OUTD);
    const uint4* e1 = (const uint4*)(g_emb2_h + (size_t)v1 * OUTD);
    const uint4* e2 = (const uint4*)(g_emb2_h + (size_t)v2 * OUTD);
    uint4 x = e0[lane], y = e1[lane], z = e2[lane];
    uint4 o;
    {
        float2 fx, fy, fz;
        fx = h2f(x.x); fy = h2f(y.x); fz = h2f(z.x);
        o.x = f2h(fmaxf(fx.x + fy.x + fz.x, 0.0f), fmaxf(fx.y + fy.y + fz.y, 0.0f));
        fx = h2f(x.y); fy = h2f(y.y); fz = h2f(z.y);
        o.y = f2h(fmaxf(fx.x + fy.x + fz.x, 0.0f), fmaxf(fx.y + fy.y + fz.y, 0.0f));
        fx = h2f(x.z); fy = h2f(y.z); fz = h2f(z.z);
        o.z = f2h(fmaxf(fx.x + fy.x + fz.x, 0.0f), fmaxf(fx.y + fy.y + fz.y, 0.0f));
        fx = h2f(x.w); fy = h2f(y.w); fz = h2f(z.w);
        o.w = f2h(fmaxf(fx.x + fy.x + fz.x, 0.0f), fmaxf(fx.y + fy.y + fz.y, 0.0f));
    }
    ((uint4*)(g_relu_s + (size_t)wg * OUTD))[lane] = o;
}

// ---------------- node gather: sum_s[v] = sum over incident edges ------------
__global__ __launch_bounds__(256) void gather_kernel() {
    int v = (blockIdx.x * blockDim.x + threadIdx.x) >> 5;
    int lane = threadIdx.x & 31;
    if (v >= N_NODES) return;
    int d = g_deg[v];
    if (d > CSRCAP) d = CSRCAP;
    float a[8];
#pragma unroll
    for (int q = 0; q < 8; q++) a[q] = 0.0f;
    for (int t = 0; t < d; t++) {
        int e = g_csr[v * CSRCAP + t];
        uint4 pk = ((const uint4*)(g_relu_s + (size_t)e * OUTD))[lane];
        float2 f0 = h2f(pk.x), f1 = h2f(pk.y), f2 = h2f(pk.z), f3 = h2f(pk.w);
        a[0] += f0.x; a[1] += f0.y; a[2] += f1.x; a[3] += f1.y;
        a[4] += f2.x; a[5] += f2.y; a[6] += f3.x; a[7] += f3.y;
    }
    float4* o = (float4*)(g_sum_s + (size_t)v * OUTD);
    o[lane * 2]     = make_float4(a[0], a[1], a[2], a[3]);
    o[lane * 2 + 1] = make_float4(a[4], a[5], a[6], a[7]);
}

// ---------------- launch ----------------------------------------------------
extern "C" void kernel_launch(void* const* d_in, const int* in_sizes, int n_in,
                              void* d_out, int out_size) {
    const float* emb = (const float*)d_in[0];
    const int*   en  = (const int*)d_in[1];
    const float* Wp  = (const float*)d_in[2];
    const float* bp  = (const float*)d_in[3];
    const float* W2a = (const float*)d_in[4];
    const float* b2a = (const float*)d_in[5];
    const float* W2b = (const float*)d_in[6];
    const float* b2b = (const float*)d_in[7];
    const float* Wq  = (const float*)d_in[8];
    const float* bq  = (const float*)d_in[9];
    float* out = (float*)d_out;

    float *p_emb_new, *p_sum_c1, *p_sum_s, *p_invdeg, *p_wq_r, *p_bias1, *p_bias2;
    __half *p_emb_h, *p_hid_h, *p_emb2_h, *p_wp_h, *p_w2a_h, *p_w2b_h;
    cudaGetSymbolAddress((void**)&p_emb_new, g_emb_new);
    cudaGetSymbolAddress((void**)&p_sum_c1,  g_sum_c1);
    cudaGetSymbolAddress((void**)&p_sum_s,   g_sum_s);
    cudaGetSymbolAddress((void**)&p_invdeg,  g_invdeg);
    cudaGetSymbolAddress((void**)&p_wq_r,    g_wq_r);
    cudaGetSymbolAddress((void**)&p_bias1,   g_bias1);
    cudaGetSymbolAddress((void**)&p_bias2,   g_bias2);
    cudaGetSymbolAddress((void**)&p_emb_h,   g_emb_h);
    cudaGetSymbolAddress((void**)&p_hid_h,   g_hid_h);
    cudaGetSymbolAddress((void**)&p_emb2_h,  g_emb2_h);
    cudaGetSymbolAddress((void**)&p_wp_h,    g_wp_h);
    cudaGetSymbolAddress((void**)&p_w2a_h,   g_w2a_h);
    cudaGetSymbolAddress((void**)&p_w2b_h,   g_w2b_h);

    constexpr size_t SH18 = smem_h(1, 8);     // 51200 (G2/G3)
    constexpr size_t SH42 = smem_h(4, 2);     // 51200 (G1)
    constexpr size_t SM18 = smem_bytes(1, 8); // 86016 (G4 tf32)
    cudaFuncSetAttribute(gemm_h<1,8,256,true, true >, cudaFuncAttributeMaxDynamicSharedMemorySize, (int)SH18);
    cudaFuncSetAttribute(gemm_h<1,8,256,false,true >, cudaFuncAttributeMaxDynamicSharedMemorySize, (int)SH18);
    cudaFuncSetAttribute(gemm_h<4,2,256,false,false>, cudaFuncAttributeMaxDynamicSharedMemorySize, (int)SH42);
    cudaFuncSetAttribute(gemm_v2<1,8,256,true>,       cudaFuncAttributeMaxDynamicSharedMemorySize, (int)SM18);

    const int M = N_NODES;

    // 1..3: prep  (slot 4 = G2 for the ncu window)
    {
        int total = FEAT * RANK + FEAT * HIDD + HIDD * OUTD + RANK * OUTD + RANK + HIDD;
        wprep_kernel<<<(total + 255) / 256, 256>>>(Wp, bp, W2a, b2a, W2b, Wq);  // 1
    }
    {
        int n4 = N_NODES * FEAT / 4;
        emb_half_kernel<<<(n4 + 255) / 256, 256>>>((const float4*)emb, n4);     // 2
    }
    zero_kernel<<<1024, 256>>>();                                               // 3

    // 4: G2: hid = relu(emb @ W2a + bias2) -> half   [64x256]
    gemm_h<1,8,256,true,true><<<dim3(HIDD / 256, (M + 63) / 64), 256, SH18>>>(
        M, HIDD, FEAT, p_emb_h, p_w2a_h, p_bias2, p_hid_h);
    // 5: G1: emb_new = emb @ Wp + bias1 -> float     [256x64]
    gemm_h<4,2,256,false,false><<<dim3(1, (M + 255) / 256), 256, SH42>>>(
        M, RANK, FEAT, p_emb_h, p_wp_h, p_bias1, p_emb_new);
    // 6: G3: emb2 = hid @ W2b + b2b -> half          [64x256]
    gemm_h<1,8,256,false,true><<<dim3(1, (M + 63) / 64), 256, SH18>>>(
        M, OUTD, HIDD, p_hid_h, p_w2b_h, b2b, p_emb2_h);
    // 7: CSR build (+degree)
    csr_kernel<<<(NEDGE * KE + 255) / 256, 256>>>(en);
    // 8: degree-derived scales
    scale_kernel<<<(N_NODES + 255) / 256, 256>>>();
    // 9: edge kernel: c1 atomics + relu_s fp16 store
    edge_kernel<<<(NEDGE * 32) / 256, 256>>>(en);
    // 10: node gather: sum_s
    gather_kernel<<<(N_NODES * 32 + 255) / 256, 256>>>();
    // 11: G4: out = relu(invdeg * (sum_c1 @ Wq + sum_s) + bq)  [tf32, CVTA]
    gemm_v2<1,8,256,true><<<dim3(1, (M + 63) / 64), 256, SM18>>>(
        M, OUTD, RANK, p_sum_c1, p_wq_r, bq, p_sum_s, p_invdeg, out);
}

// round 15
// speedup vs baseline: 1.3611x; 1.3611x over previous
#include <cuda_runtime.h>
#include <cuda_fp16.h>
#include <math.h>
#include <stdint.h>

#define N_NODES 100000
#define FEAT    256
#define RANK    64
#define HIDD    512
#define OUTD    256
#define NEDGE   200000
#define KE      3
#define CSRCAP  12

// ---------------- scratch (device globals; no allocations allowed) ----------
__device__ __align__(16) float  g_emb_new[N_NODES * RANK];
__device__ __align__(16) __half g_hid_h[(size_t)N_NODES * HIDD];
__device__ __align__(16) __half g_emb2_h[(size_t)N_NODES * OUTD];
__device__ __align__(16) float  g_sum_c1[N_NODES * RANK];
__device__ __align__(16) float  g_sum_s[N_NODES * OUTD];
__device__ __align__(16) __half g_relu_s[(size_t)NEDGE * OUTD];
__device__ __align__(16) __half g_emb_h[(size_t)N_NODES * FEAT];
__device__ __align__(16) __half g_wp_h[RANK * FEAT];                 // [N][K]
__device__ __align__(16) __half g_w2a_h[HIDD * FEAT];
__device__ __align__(16) __half g_w2b_h[OUTD * HIDD];
__device__ __align__(16) float  g_wq_r[RANK * OUTD];                 // tf32 [K][N]
__device__ __align__(16) float  g_bias1[RANK];
__device__ __align__(16) float  g_bias2[HIDD];
__device__ int   g_csr[N_NODES * CSRCAP];
__device__ int   g_deg[N_NODES];
__device__ float g_dscale[N_NODES];
__device__ float g_invdeg[N_NODES];

__device__ __forceinline__ float tf32r(float x) {
    uint32_t r;
    asm("cvt.rna.tf32.f32 %0, %1;" : "=r"(r) : "f"(x));
    return __uint_as_float(r);
}
__device__ __forceinline__ uint32_t tf32u(float x) {
    uint32_t r;
    asm("cvt.rna.tf32.f32 %0, %1;" : "=r"(r) : "f"(x));
    return r;
}

// ---------------- utility kernels -------------------------------------------
__global__ void zero_kernel() {
    int i = blockIdx.x * blockDim.x + threadIdx.x;
    int stride = gridDim.x * blockDim.x;
    float4 z = make_float4(0.f, 0.f, 0.f, 0.f);
    float4* c4 = (float4*)g_sum_c1;
    for (int t = i; t < N_NODES * RANK / 4; t += stride) c4[t] = z;
    for (int t = i; t < N_NODES; t += stride) g_deg[t] = 0;
}

__global__ void csr_kernel(const int* __restrict__ en) {
    int i = blockIdx.x * blockDim.x + threadIdx.x;
    if (i < NEDGE * KE) {
        int v = en[i];
        int pos = atomicAdd(&g_deg[v], 1);
        if (pos < CSRCAP) g_csr[v * CSRCAP + pos] = i / KE;
    }
}

__global__ void scale_kernel() {
    int v = blockIdx.x * blockDim.x + threadIdx.x;
    if (v < N_NODES) {
        float d = (float)g_deg[v];
        g_dscale[v] = cbrtf(d);
        g_invdeg[v] = 1.0f / d;
    }
}

__global__ void emb_half_kernel(const float4* __restrict__ src, int n4) {
    int i = blockIdx.x * blockDim.x + threadIdx.x;
    if (i < n4) {
        float4 v = src[i];
        __half2 h0 = __float22half2_rn(make_float2(v.x, v.y));
        __half2 h1 = __float22half2_rn(make_float2(v.z, v.w));
        uint2 pk;
        pk.x = *(uint32_t*)&h0;
        pk.y = *(uint32_t*)&h1;
        ((uint2*)g_emb_h)[i] = pk;
    }
}

__global__ void wprep_kernel(const float* __restrict__ Wp,  const float* __restrict__ bp,
                             const float* __restrict__ W2a, const float* __restrict__ b2a,
                             const float* __restrict__ W2b,
                             const float* __restrict__ Wq) {
    const int S1 = FEAT * RANK;
    const int S2 = S1 + FEAT * HIDD;
    const int S3 = S2 + HIDD * OUTD;
    const int S4 = S3 + RANK * OUTD;
    const int S5 = S4 + RANK;
    const int S6 = S5 + HIDD;
    int i = blockIdx.x * blockDim.x + threadIdx.x;
    if (i < S1) {
        int k = i / RANK, n = i % RANK;
        g_wp_h[n * FEAT + k] = __float2half_rn(Wp[i]);
    } else if (i < S2) {
        int j = i - S1;
        int k = j / HIDD, n = j % HIDD;
        g_w2a_h[n * FEAT + k] = __float2half_rn(W2a[j]);
    } else if (i < S3) {
        int j = i - S2;
        int k = j / OUTD, n = j % OUTD;
        g_w2b_h[n * HIDD + k] = __float2half_rn(W2b[j]);
    } else if (i < S4) {
        int j = i - S3;
        g_wq_r[j] = tf32r(Wq[j]);
    } else if (i < S5) {
        int j = i - S4;
        g_bias1[j] = Wp[FEAT * RANK + j] + bp[j];
    } else if (i < S6) {
        int j = i - S5;
        g_bias2[j] = W2a[FEAT * HIDD + j] + b2a[j];
    }
}

// ---------------- fp16 GEMM with ldmatrix fragment loads ---------------------
// A[M,K] half row-major, Bt[N,K] half. BK=32, warp tile 64x32 (4x4 m16n8k16).
template <int WMW, int WNW, int TPB, bool RELU, bool OUTHALF>
__global__ __launch_bounds__(TPB) void gemm_h(
    int M, int N, int K,
    const __half* __restrict__ A, const __half* __restrict__ Bt,
    const float* __restrict__ bias, void* __restrict__ Cv)
{
    constexpr int BM = WMW * 64, BN = WNW * 32, BK = 32;
    constexpr int AST = 40;                 // halves/row (80B) -> LDSM conflict-free
    constexpr int BST = 40;
    constexpr int ATILE = BM * AST;         // halves
    constexpr int BTILE = BN * BST;
    constexpr int CA = BM * 4 / TPB;
    constexpr int CB = BN * 4 / TPB;
    static_assert(CA >= 1 && CB >= 1, "tile/thread mismatch");
    static_assert(WMW * WNW * 32 == TPB, "warp layout mismatch");

    extern __shared__ __half smemh[];
    __half* AsB = smemh;
    __half* BsB = smemh + 2 * ATILE;

    int tid = threadIdx.x;
    int warp = tid >> 5, lane = tid & 31;
    int wm = warp / WNW, wn = warp % WNW;
    int lr = lane >> 2, lc = lane & 3;
    int block_m = blockIdx.y * BM, block_n = blockIdx.x * BN;

    // ldmatrix per-lane selectors
    int lid8 = lane & 7;
    int jrow = (lane >> 3) & 1;     // matrix row-half / k-half selector
    int jcol = lane >> 4;           // matrix col-half / n-half selector

    uint32_t As_base = (uint32_t)__cvta_generic_to_shared(AsB);
    uint32_t Bs_base = (uint32_t)__cvta_generic_to_shared(BsB);

    // byte offsets (invariant across iters/buffers; ks adds 32B)
    uint32_t a_off[4], b_off[2];
#pragma unroll
    for (int mt = 0; mt < 4; mt++)
        a_off[mt] = (uint32_t)(((wm * 64 + mt * 16 + jrow * 8 + lid8) * AST + jcol * 8) * 2);
#pragma unroll
    for (int p = 0; p < 2; p++)
        b_off[p] = (uint32_t)(((wn * 32 + p * 16 + jcol * 8 + lid8) * BST + jrow * 8) * 2);

    float acc[4][4][4];
#pragma unroll
    for (int a = 0; a < 4; a++)
#pragma unroll
        for (int b = 0; b < 4; b++)
#pragma unroll
            for (int c = 0; c < 4; c++) acc[a][b][c] = 0.0f;

    auto load_tiles = [&](int it, __half* As, __half* Bs) {
#pragma unroll
        for (int i = 0; i < CA; i++) {
            int f = tid + TPB * i;
            int m = f >> 2, q = f & 3;
            int gr = block_m + m;
            uint32_t dst = (uint32_t)__cvta_generic_to_shared(As + m * AST + 8 * q);
            const __half* src = A + (size_t)gr * K + it * BK + 8 * q;
            int sz = (gr < M) ? 16 : 0;
            asm volatile("cp.async.cg.shared.global [%0], [%1], 16, %2;"
                         :: "r"(dst), "l"(src), "r"(sz));
        }
#pragma unroll
        for (int i = 0; i < CB; i++) {
            int f = tid + TPB * i;
            int n = f >> 2, q = f & 3;
            uint32_t dst = (uint32_t)__cvta_generic_to_shared(Bs + n * BST + 8 * q);
            const __half* src = Bt + (size_t)(block_n + n) * K + it * BK + 8 * q;
            asm volatile("cp.async.cg.shared.global [%0], [%1], 16;"
                         :: "r"(dst), "l"(src));
        }
        asm volatile("cp.async.commit_group;");
    };

    int nIter = K / BK;
    load_tiles(0, AsB, BsB);

    for (int it = 0; it < nIter; ++it) {
        int buf = it & 1;
        if (it + 1 < nIter) {
            load_tiles(it + 1, AsB + (buf ^ 1) * ATILE, BsB + (buf ^ 1) * BTILE);
            asm volatile("cp.async.wait_group 1;");
        } else {
            asm volatile("cp.async.wait_group 0;");
        }
        __syncthreads();
        uint32_t abase = As_base + (uint32_t)(buf * ATILE * 2);
        uint32_t bbase = Bs_base + (uint32_t)(buf * BTILE * 2);

#pragma unroll
        for (int ks = 0; ks < 2; ks++) {
            uint32_t af[4][4], bf[4][2];
#pragma unroll
            for (int mt = 0; mt < 4; mt++) {
                asm volatile(
                    "ldmatrix.sync.aligned.m8n8.x4.shared.b16 {%0,%1,%2,%3}, [%4];"
                    : "=r"(af[mt][0]), "=r"(af[mt][1]), "=r"(af[mt][2]), "=r"(af[mt][3])
                    : "r"(abase + a_off[mt] + ks * 32));
            }
#pragma unroll
            for (int p = 0; p < 2; p++) {
                asm volatile(
                    "ldmatrix.sync.aligned.m8n8.x4.shared.b16 {%0,%1,%2,%3}, [%4];"
                    : "=r"(bf[2 * p][0]), "=r"(bf[2 * p][1]),
                      "=r"(bf[2 * p + 1][0]), "=r"(bf[2 * p + 1][1])
                    : "r"(bbase + b_off[p] + ks * 32));
            }
#pragma unroll
            for (int mt = 0; mt < 4; mt++)
#pragma unroll
                for (int nt = 0; nt < 4; nt++)
                    asm volatile(
                        "mma.sync.aligned.m16n8k16.row.col.f32.f16.f16.f32 "
                        "{%0,%1,%2,%3}, {%4,%5,%6,%7}, {%8,%9}, {%0,%1,%2,%3};"
                        : "+f"(acc[mt][nt][0]), "+f"(acc[mt][nt][1]),
                          "+f"(acc[mt][nt][2]), "+f"(acc[mt][nt][3])
                        : "r"(af[mt][0]), "r"(af[mt][1]), "r"(af[mt][2]), "r"(af[mt][3]),
                          "r"(bf[nt][0]), "r"(bf[nt][1]));
        }
        __syncthreads();
    }

    // epilogue
#pragma unroll
    for (int mt = 0; mt < 4; mt++) {
#pragma unroll
        for (int half_i = 0; half_i < 2; half_i++) {
            int row = block_m + wm * 64 + mt * 16 + lr + half_i * 8;
            if (row >= M) continue;
#pragma unroll
            for (int nt = 0; nt < 4; nt++) {
                int gc = block_n + wn * 32 + nt * 8 + 2 * lc;
                float v0 = acc[mt][nt][half_i * 2 + 0] + bias[gc];
                float v1 = acc[mt][nt][half_i * 2 + 1] + bias[gc + 1];
                if (RELU) { v0 = fmaxf(v0, 0.0f); v1 = fmaxf(v1, 0.0f); }
                if (OUTHALF) {
                    __half2 h = __float22half2_rn(make_float2(v0, v1));
                    *(__half2*)((__half*)Cv + (size_t)row * N + gc) = h;
                } else {
                    *(float2*)((float*)Cv + (size_t)row * N + gc) = make_float2(v0, v1);
                }
            }
        }
    }
}

constexpr size_t smem_h(int WMW, int WNW) {
    return (size_t)(2 * (WMW * 64) * 40 + 2 * (WNW * 32) * 40) * 2;
}

// ---------------- TF32 GEMM (G4 only) ----------------------------------------
template <int WMW, int WNW, int TPB, bool RELU>
__global__ __launch_bounds__(TPB) void gemm_v2(
    int M, int N, int K,
    const float* __restrict__ A, const float* __restrict__ B,
    const float* __restrict__ bias,
    const float* __restrict__ D, const float* __restrict__ rowscale,
    float* __restrict__ C)
{
    constexpr int BM = WMW * 64, BN = WNW * 32, BK = 32;
    constexpr int AST = BK + 4;
    constexpr int BST = BN + 8;
    constexpr int ATILE = BM * AST;
    constexpr int BTILE = BK * BST;
    constexpr int CA = BM * BK / (4 * TPB);
    constexpr int CB = BK * BN / (4 * TPB);
    static_assert(CA >= 1 && CB >= 1, "tile/thread mismatch");
    static_assert(WMW * WNW * 32 == TPB, "warp layout mismatch");

    extern __shared__ float smem[];
    float* AsB = smem;
    float* BsB = smem + 2 * ATILE;

    int tid = threadIdx.x;
    int warp = tid >> 5, lane = tid & 31;
    int wm = warp / WNW, wn = warp % WNW;
    int lr = lane >> 2, lc = lane & 3;
    int block_m = blockIdx.y * BM, block_n = blockIdx.x * BN;

    float acc[4][4][4];
#pragma unroll
    for (int a = 0; a < 4; a++)
#pragma unroll
        for (int b = 0; b < 4; b++)
#pragma unroll
            for (int c = 0; c < 4; c++) acc[a][b][c] = 0.0f;

    auto load_tiles = [&](int it, float* As, float* Bs) {
#pragma unroll
        for (int i = 0; i < CA; i++) {
            int f = tid + TPB * i;
            int m = f >> 3, q = f & 7;
            int gr = block_m + m;
            uint32_t dst = (uint32_t)__cvta_generic_to_shared(As + m * AST + 4 * q);
            const float* src = A + (size_t)gr * K + it * BK + 4 * q;
            int sz = (gr < M) ? 16 : 0;
            asm volatile("cp.async.cg.shared.global [%0], [%1], 16, %2;"
                         :: "r"(dst), "l"(src), "r"(sz));
        }
#pragma unroll
        for (int i = 0; i < CB; i++) {
            int f = tid + TPB * i;
            int n4 = f % (BN / 4), k = f / (BN / 4);
            uint32_t dst = (uint32_t)__cvta_generic_to_shared(Bs + k * BST + 4 * n4);
            const float* src = B + (size_t)(it * BK + k) * N + block_n + 4 * n4;
            asm volatile("cp.async.cg.shared.global [%0], [%1], 16;"
                         :: "r"(dst), "l"(src));
        }
        asm volatile("cp.async.commit_group;");
    };

    int nIter = K / BK;
    load_tiles(0, AsB, BsB);

    for (int it = 0; it < nIter; ++it) {
        int buf = it & 1;
        if (it + 1 < nIter) {
            load_tiles(it + 1, AsB + (buf ^ 1) * ATILE, BsB + (buf ^ 1) * BTILE);
            asm volatile("cp.async.wait_group 1;");
        } else {
            asm volatile("cp.async.wait_group 0;");
        }
        __syncthreads();
        const float* As = AsB + buf * ATILE;
        const float* Bs = BsB + buf * BTILE;

#pragma unroll
        for (int ks = 0; ks < 4; ks++) {
            int col = ks * 8 + lc;
            uint32_t af[4][4], bfr[4][2];
#pragma unroll
            for (int mt = 0; mt < 4; mt++) {
                const float* ap = As + (wm * 64 + mt * 16 + lr) * AST + col;
                af[mt][0] = tf32u(ap[0]);
                af[mt][1] = tf32u(ap[8 * AST]);
                af[mt][2] = tf32u(ap[4]);
                af[mt][3] = tf32u(ap[8 * AST + 4]);
            }
#pragma unroll
            for (int nt = 0; nt < 4; nt++) {
                const float* bp = Bs + col * BST + wn * 32 + nt * 8 + lr;
                bfr[nt][0] = __float_as_uint(bp[0]);
                bfr[nt][1] = __float_as_uint(bp[4 * BST]);
            }
#pragma unroll
            for (int mt = 0; mt < 4; mt++)
#pragma unroll
                for (int nt = 0; nt < 4; nt++)
                    asm volatile(
                        "mma.sync.aligned.m16n8k8.row.col.f32.tf32.tf32.f32 "
                        "{%0,%1,%2,%3}, {%4,%5,%6,%7}, {%8,%9}, {%0,%1,%2,%3};"
                        : "+f"(acc[mt][nt][0]), "+f"(acc[mt][nt][1]),
                          "+f"(acc[mt][nt][2]), "+f"(acc[mt][nt][3])
                        : "r"(af[mt][0]), "r"(af[mt][1]), "r"(af[mt][2]), "r"(af[mt][3]),
                          "r"(bfr[nt][0]), "r"(bfr[nt][1]));
        }
        __syncthreads();
    }

#pragma unroll
    for (int mt = 0; mt < 4; mt++) {
#pragma unroll
        for (int half_i = 0; half_i < 2; half_i++) {
            int row = block_m + wm * 64 + mt * 16 + lr + half_i * 8;
            if (row >= M) continue;
            float rs = rowscale[row];
#pragma unroll
            for (int nt = 0; nt < 4; nt++) {
                int gc = block_n + wn * 32 + nt * 8 + 2 * lc;
                float v0 = acc[mt][nt][half_i * 2 + 0];
                float v1 = acc[mt][nt][half_i * 2 + 1];
                float2 d = *(const float2*)(D + (size_t)row * N + gc);
                v0 += d.x; v1 += d.y;
                v0 = rs * v0 + bias[gc];
                v1 = rs * v1 + bias[gc + 1];
                if (RELU) { v0 = fmaxf(v0, 0.0f); v1 = fmaxf(v1, 0.0f); }
                *(float2*)(C + (size_t)row * N + gc) = make_float2(v0, v1);
            }
        }
    }
}

constexpr size_t smem_bytes(int WMW, int WNW) {
    return (size_t)(2 * (WMW * 64) * 36 + 2 * 32 * (WNW * 32 + 8)) * 4;
}

// ---------------- edge kernel (c1 atomics + relu_s fp16 store) ---------------
__device__ __forceinline__ void red4(float* p, float4 v) {
    asm volatile("red.global.add.v4.f32 [%0], {%1,%2,%3,%4};"
                 :: "l"(p), "f"(v.x), "f"(v.y), "f"(v.z), "f"(v.w) : "memory");
}
__device__ __forceinline__ float2 h2f(uint32_t u) {
    return __half22float2(*(__half2*)&u);
}
__device__ __forceinline__ uint32_t f2h(float a, float b) {
    __half2 h = __float22half2_rn(make_float2(a, b));
    return *(uint32_t*)&h;
}

__global__ __launch_bounds__(256) void edge_kernel(const int* __restrict__ en) {
    int wg = (blockIdx.x * blockDim.x + threadIdx.x) >> 5;
    int lane = threadIdx.x & 31;
    if (wg >= NEDGE) return;
    int v0 = en[wg * 3 + 0];
    int v1 = en[wg * 3 + 1];
    int v2 = en[wg * 3 + 2];
    float d0 = g_dscale[v0], d1 = g_dscale[v1], d2 = g_dscale[v2];

    if (lane < 16) {
        float4 a = *(const float4*)(g_emb_new + (size_t)v0 * RANK + lane * 4);
        float4 b = *(const float4*)(g_emb_new + (size_t)v1 * RANK + lane * 4);
        float4 c = *(const float4*)(g_emb_new + (size_t)v2 * RANK + lane * 4);
        a.x *= d0; a.y *= d0; a.z *= d0; a.w *= d0;
        b.x *= d1; b.y *= d1; b.z *= d1; b.w *= d1;
        c.x *= d2; c.y *= d2; c.z *= d2; c.w *= d2;
        float h0 = 0.5f * d0, h1 = 0.5f * d1, h2 = 0.5f * d2;
        float4 o0 = make_float4(h0 * b.x * c.x, h0 * b.y * c.y, h0 * b.z * c.z, h0 * b.w * c.w);
        float4 o1 = make_float4(h1 * a.x * c.x, h1 * a.y * c.y, h1 * a.z * c.z, h1 * a.w * c.w);
        float4 o2 = make_float4(h2 * a.x * b.x, h2 * a.y * b.y, h2 * a.z * b.z, h2 * a.w * b.w);
        red4(g_sum_c1 + (size_t)v0 * RANK + lane * 4, o0);
        red4(g_sum_c1 + (size_t)v1 * RANK + lane * 4, o1);
        red4(g_sum_c1 + (size_t)v2 * RANK + lane * 4, o2);
    }

    const uint4* e0 = (const uint4*)(g_emb2_h + (size_t)v0 * OUTD);
    const uint4* e1 = (const uint4*)(g_emb2_h + (size_t)v1 * OUTD);
    const uint4* e2 = (const uint4*)(g_emb2_h + (size_t)v2 * OUTD);
    uint4 x = e0[lane], y = e1[lane], z = e2[lane];
    uint4 o;
    {
        float2 fx, fy, fz;
        fx = h2f(x.x); fy = h2f(y.x); fz = h2f(z.x);
        o.x = f2h(fmaxf(fx.x + fy.x + fz.x, 0.0f), fmaxf(fx.y + fy.y + fz.y, 0.0f));
        fx = h2f(x.y); fy = h2f(y.y); fz = h2f(z.y);
        o.y = f2h(fmaxf(fx.x + fy.x + fz.x, 0.0f), fmaxf(fx.y + fy.y + fz.y, 0.0f));
        fx = h2f(x.z); fy = h2f(y.z); fz = h2f(z.z);
        o.z = f2h(fmaxf(fx.x + fy.x + fz.x, 0.0f), fmaxf(fx.y + fy.y + fz.y, 0.0f));
        fx = h2f(x.w); fy = h2f(y.w); fz = h2f(z.w);
        o.w = f2h(fmaxf(fx.x + fy.x + fz.x, 0.0f), fmaxf(fx.y + fy.y + fz.y, 0.0f));
    }
    ((uint4*)(g_relu_s + (size_t)wg * OUTD))[lane] = o;
}

// ---------------- node gather: sum_s[v] = sum over incident edges ------------
__global__ __launch_bounds__(256) void gather_kernel() {
    int v = (blockIdx.x * blockDim.x + threadIdx.x) >> 5;
    int lane = threadIdx.x & 31;
    if (v >= N_NODES) return;
    int d = g_deg[v];
    if (d > CSRCAP) d = CSRCAP;
    float a[8];
#pragma unroll
    for (int q = 0; q < 8; q++) a[q] = 0.0f;
    for (int t = 0; t < d; t++) {
        int e = g_csr[v * CSRCAP + t];
        uint4 pk = ((const uint4*)(g_relu_s + (size_t)e * OUTD))[lane];
        float2 f0 = h2f(pk.x), f1 = h2f(pk.y), f2 = h2f(pk.z), f3 = h2f(pk.w);
        a[0] += f0.x; a[1] += f0.y; a[2] += f1.x; a[3] += f1.y;
        a[4] += f2.x; a[5] += f2.y; a[6] += f3.x; a[7] += f3.y;
    }
    float4* o = (float4*)(g_sum_s + (size_t)v * OUTD);
    o[lane * 2]     = make_float4(a[0], a[1], a[2], a[3]);
    o[lane * 2 + 1] = make_float4(a[4], a[5], a[6], a[7]);
}

// ---------------- launch ----------------------------------------------------
extern "C" void kernel_launch(void* const* d_in, const int* in_sizes, int n_in,
                              void* d_out, int out_size) {
    const float* emb = (const float*)d_in[0];
    const int*   en  = (const int*)d_in[1];
    const float* Wp  = (const float*)d_in[2];
    const float* bp  = (const float*)d_in[3];
    const float* W2a = (const float*)d_in[4];
    const float* b2a = (const float*)d_in[5];
    const float* W2b = (const float*)d_in[6];
    const float* b2b = (const float*)d_in[7];
    const float* Wq  = (const float*)d_in[8];
    const float* bq  = (const float*)d_in[9];
    float* out = (float*)d_out;

    float *p_emb_new, *p_sum_c1, *p_sum_s, *p_invdeg, *p_wq_r, *p_bias1, *p_bias2;
    __half *p_emb_h, *p_hid_h, *p_emb2_h, *p_wp_h, *p_w2a_h, *p_w2b_h;
    cudaGetSymbolAddress((void**)&p_emb_new, g_emb_new);
    cudaGetSymbolAddress((void**)&p_sum_c1,  g_sum_c1);
    cudaGetSymbolAddress((void**)&p_sum_s,   g_sum_s);
    cudaGetSymbolAddress((void**)&p_invdeg,  g_invdeg);
    cudaGetSymbolAddress((void**)&p_wq_r,    g_wq_r);
    cudaGetSymbolAddress((void**)&p_bias1,   g_bias1);
    cudaGetSymbolAddress((void**)&p_bias2,   g_bias2);
    cudaGetSymbolAddress((void**)&p_emb_h,   g_emb_h);
    cudaGetSymbolAddress((void**)&p_hid_h,   g_hid_h);
    cudaGetSymbolAddress((void**)&p_emb2_h,  g_emb2_h);
    cudaGetSymbolAddress((void**)&p_wp_h,    g_wp_h);
    cudaGetSymbolAddress((void**)&p_w2a_h,   g_w2a_h);
    cudaGetSymbolAddress((void**)&p_w2b_h,   g_w2b_h);

    constexpr size_t SH18 = smem_h(1, 8);
    constexpr size_t SH42 = smem_h(4, 2);
    constexpr size_t SM18 = smem_bytes(1, 8);
    cudaFuncSetAttribute(gemm_h<1,8,256,true, true >, cudaFuncAttributeMaxDynamicSharedMemorySize, (int)SH18);
    cudaFuncSetAttribute(gemm_h<1,8,256,false,true >, cudaFuncAttributeMaxDynamicSharedMemorySize, (int)SH18);
    cudaFuncSetAttribute(gemm_h<4,2,256,false,false>, cudaFuncAttributeMaxDynamicSharedMemorySize, (int)SH42);
    cudaFuncSetAttribute(gemm_v2<1,8,256,true>,       cudaFuncAttributeMaxDynamicSharedMemorySize, (int)SM18);

    const int M = N_NODES;

    // 1..3: prep  (slot 4 = G2 for the ncu window)
    {
        int total = FEAT * RANK + FEAT * HIDD + HIDD * OUTD + RANK * OUTD + RANK + HIDD;
        wprep_kernel<<<(total + 255) / 256, 256>>>(Wp, bp, W2a, b2a, W2b, Wq);  // 1
    }
    {
        int n4 = N_NODES * FEAT / 4;
        emb_half_kernel<<<(n4 + 255) / 256, 256>>>((const float4*)emb, n4);     // 2
    }
    zero_kernel<<<1024, 256>>>();                                               // 3

    // 4: G2: hid = relu(emb @ W2a + bias2) -> half   [64x256]
    gemm_h<1,8,256,true,true><<<dim3(HIDD / 256, (M + 63) / 64), 256, SH18>>>(
        M, HIDD, FEAT, p_emb_h, p_w2a_h, p_bias2, p_hid_h);
    // 5: G1: emb_new = emb @ Wp + bias1 -> float     [256x64]
    gemm_h<4,2,256,false,false><<<dim3(1, (M + 255) / 256), 256, SH42>>>(
        M, RANK, FEAT, p_emb_h, p_wp_h, p_bias1, p_emb_new);
    // 6: G3: emb2 = hid @ W2b + b2b -> half          [64x256]
    gemm_h<1,8,256,false,true><<<dim3(1, (M + 63) / 64), 256, SH18>>>(
        M, OUTD, HIDD, p_hid_h, p_w2b_h, b2b, p_emb2_h);
    // 7: CSR build (+degree)
    csr_kernel<<<(NEDGE * KE + 255) / 256, 256>>>(en);
    // 8: degree-derived scales
    scale_kernel<<<(N_NODES + 255) / 256, 256>>>();
    // 9: edge kernel: c1 atomics + relu_s fp16 store
    edge_kernel<<<(NEDGE * 32) / 256, 256>>>(en);
    // 10: node gather: sum_s
    gather_kernel<<<(N_NODES * 32 + 255) / 256, 256>>>();
    // 11: G4: out = relu(invdeg * (sum_c1 @ Wq + sum_s) + bq)  [tf32, CVTA]
    gemm_v2<1,8,256,true><<<dim3(1, (M + 63) / 64), 256, SM18>>>(
        M, OUTD, RANK, p_sum_c1, p_wq_r, bq, p_sum_s, p_invdeg, out);
}

// round 16
// speedup vs baseline: 1.3800x; 1.0139x over previous
#include <cuda_runtime.h>
#include <cuda_fp16.h>
#include <math.h>
#include <stdint.h>

#define N_NODES 100000
#define FEAT    256
#define RANK    64
#define HIDD    512
#define OUTD    256
#define NEDGE   200000
#define KE      3
#define CSRCAP  12

// ---------------- scratch (device globals; no allocations allowed) ----------
__device__ __align__(16) float  g_emb_new[N_NODES * RANK];
__device__ __align__(16) __half g_hid_h[(size_t)N_NODES * HIDD];
__device__ __align__(16) __half g_emb2_h[(size_t)N_NODES * OUTD];
__device__ __align__(16) float  g_sum_c1[N_NODES * RANK];
__device__ __align__(16) float  g_sum_s[N_NODES * OUTD];
__device__ __align__(16) __half g_relu_s[(size_t)NEDGE * OUTD];
__device__ __align__(16) __half g_emb_h[(size_t)N_NODES * FEAT];
__device__ __align__(16) __half g_wp_h[RANK * FEAT];                 // [N][K]
__device__ __align__(16) __half g_w2a_h[HIDD * FEAT];
__device__ __align__(16) __half g_w2b_h[OUTD * HIDD];
__device__ __align__(16) float  g_wq_r[RANK * OUTD];                 // tf32 [K][N]
__device__ __align__(16) float  g_bias1[RANK];
__device__ __align__(16) float  g_bias2[HIDD];
__device__ int   g_csr[N_NODES * CSRCAP];
__device__ int   g_deg[N_NODES];
__device__ float g_dscale[N_NODES];
__device__ float g_invdeg[N_NODES];

__device__ __forceinline__ float tf32r(float x) {
    uint32_t r;
    asm("cvt.rna.tf32.f32 %0, %1;" : "=r"(r) : "f"(x));
    return __uint_as_float(r);
}
__device__ __forceinline__ uint32_t tf32u(float x) {
    uint32_t r;
    asm("cvt.rna.tf32.f32 %0, %1;" : "=r"(r) : "f"(x));
    return r;
}

// ---------------- utility kernels -------------------------------------------
__global__ void zero_kernel() {
    int i = blockIdx.x * blockDim.x + threadIdx.x;
    int stride = gridDim.x * blockDim.x;
    float4 z = make_float4(0.f, 0.f, 0.f, 0.f);
    float4* c4 = (float4*)g_sum_c1;
    for (int t = i; t < N_NODES * RANK / 4; t += stride) c4[t] = z;
    for (int t = i; t < N_NODES; t += stride) g_deg[t] = 0;
}

__global__ void csr_kernel(const int* __restrict__ en) {
    int i = blockIdx.x * blockDim.x + threadIdx.x;
    if (i < NEDGE * KE) {
        int v = en[i];
        int pos = atomicAdd(&g_deg[v], 1);
        if (pos < CSRCAP) g_csr[v * CSRCAP + pos] = i / KE;
    }
}

__global__ void scale_kernel() {
    int v = blockIdx.x * blockDim.x + threadIdx.x;
    if (v < N_NODES) {
        float d = (float)g_deg[v];
        g_dscale[v] = cbrtf(d);
        g_invdeg[v] = 1.0f / d;
    }
}

__global__ void emb_half_kernel(const float4* __restrict__ src, int n4) {
    int i = blockIdx.x * blockDim.x + threadIdx.x;
    if (i < n4) {
        float4 v = src[i];
        __half2 h0 = __float22half2_rn(make_float2(v.x, v.y));
        __half2 h1 = __float22half2_rn(make_float2(v.z, v.w));
        uint2 pk;
        pk.x = *(uint32_t*)&h0;
        pk.y = *(uint32_t*)&h1;
        ((uint2*)g_emb_h)[i] = pk;
    }
}

__global__ void wprep_kernel(const float* __restrict__ Wp,  const float* __restrict__ bp,
                             const float* __restrict__ W2a, const float* __restrict__ b2a,
                             const float* __restrict__ W2b,
                             const float* __restrict__ Wq) {
    const int S1 = FEAT * RANK;
    const int S2 = S1 + FEAT * HIDD;
    const int S3 = S2 + HIDD * OUTD;
    const int S4 = S3 + RANK * OUTD;
    const int S5 = S4 + RANK;
    const int S6 = S5 + HIDD;
    int i = blockIdx.x * blockDim.x + threadIdx.x;
    if (i < S1) {
        int k = i / RANK, n = i % RANK;
        g_wp_h[n * FEAT + k] = __float2half_rn(Wp[i]);
    } else if (i < S2) {
        int j = i - S1;
        int k = j / HIDD, n = j % HIDD;
        g_w2a_h[n * FEAT + k] = __float2half_rn(W2a[j]);
    } else if (i < S3) {
        int j = i - S2;
        int k = j / OUTD, n = j % OUTD;
        g_w2b_h[n * HIDD + k] = __float2half_rn(W2b[j]);
    } else if (i < S4) {
        int j = i - S3;
        g_wq_r[j] = tf32r(Wq[j]);
    } else if (i < S5) {
        int j = i - S4;
        g_bias1[j] = Wp[FEAT * RANK + j] + bp[j];
    } else if (i < S6) {
        int j = i - S5;
        g_bias2[j] = W2a[FEAT * HIDD + j] + b2a[j];
    }
}

// ---------------- fp16 GEMM: ldmatrix + 3-stage cp.async pipeline ------------
// A[M,K] half row-major, Bt[N,K] half. BK=32, warp tile 64x32 (4x4 m16n8k16).
template <int WMW, int WNW, int TPB, bool RELU, bool OUTHALF>
__global__ __launch_bounds__(TPB) void gemm_h(
    int M, int N, int K,
    const __half* __restrict__ A, const __half* __restrict__ Bt,
    const float* __restrict__ bias, void* __restrict__ Cv)
{
    constexpr int BM = WMW * 64, BN = WNW * 32, BK = 32;
    constexpr int AST = 40;                 // halves/row (80B) -> LDSM conflict-free
    constexpr int BST = 40;
    constexpr int ATILE = BM * AST;         // halves
    constexpr int BTILE = BN * BST;
    constexpr int STAGE = ATILE + BTILE;    // halves per stage (A then B)
    constexpr int CA = BM * 4 / TPB;
    constexpr int CB = BN * 4 / TPB;
    static_assert(CA >= 1 && CB >= 1, "tile/thread mismatch");
    static_assert(WMW * WNW * 32 == TPB, "warp layout mismatch");

    extern __shared__ __half smemh[];

    int tid = threadIdx.x;
    int warp = tid >> 5, lane = tid & 31;
    int wm = warp / WNW, wn = warp % WNW;
    int lr = lane >> 2, lc = lane & 3;
    int block_m = blockIdx.y * BM, block_n = blockIdx.x * BN;

    // ldmatrix per-lane selectors
    int lid8 = lane & 7;
    int jrow = (lane >> 3) & 1;
    int jcol = lane >> 4;

    uint32_t S_base = (uint32_t)__cvta_generic_to_shared(smemh);

    uint32_t a_off[4], b_off[2];
#pragma unroll
    for (int mt = 0; mt < 4; mt++)
        a_off[mt] = (uint32_t)(((wm * 64 + mt * 16 + jrow * 8 + lid8) * AST + jcol * 8) * 2);
#pragma unroll
    for (int p = 0; p < 2; p++)
        b_off[p] = (uint32_t)((ATILE + (wn * 32 + p * 16 + jcol * 8 + lid8) * BST + jrow * 8) * 2);

    float acc[4][4][4];
#pragma unroll
    for (int a = 0; a < 4; a++)
#pragma unroll
        for (int b = 0; b < 4; b++)
#pragma unroll
            for (int c = 0; c < 4; c++) acc[a][b][c] = 0.0f;

    auto load_tiles = [&](int it, int stg) {
        __half* As = smemh + stg * STAGE;
        __half* Bs = As + ATILE;
#pragma unroll
        for (int i = 0; i < CA; i++) {
            int f = tid + TPB * i;
            int m = f >> 2, q = f & 3;
            int gr = block_m + m;
            uint32_t dst = (uint32_t)__cvta_generic_to_shared(As + m * AST + 8 * q);
            const __half* src = A + (size_t)gr * K + it * BK + 8 * q;
            int sz = (gr < M) ? 16 : 0;
            asm volatile("cp.async.cg.shared.global [%0], [%1], 16, %2;"
                         :: "r"(dst), "l"(src), "r"(sz));
        }
#pragma unroll
        for (int i = 0; i < CB; i++) {
            int f = tid + TPB * i;
            int n = f >> 2, q = f & 3;
            uint32_t dst = (uint32_t)__cvta_generic_to_shared(Bs + n * BST + 8 * q);
            const __half* src = Bt + (size_t)(block_n + n) * K + it * BK + 8 * q;
            asm volatile("cp.async.cg.shared.global [%0], [%1], 16;"
                         :: "r"(dst), "l"(src));
        }
        asm volatile("cp.async.commit_group;");
    };

    int nIter = K / BK;
    load_tiles(0, 0);
    if (nIter > 1) load_tiles(1, 1);

    int stg = 0;
    for (int it = 0; it < nIter; ++it) {
        if (it + 1 < nIter) asm volatile("cp.async.wait_group 1;");
        else                asm volatile("cp.async.wait_group 0;");
        __syncthreads();
        if (it + 2 < nIter) {
            int nstg = stg + 2; if (nstg >= 3) nstg -= 3;
            load_tiles(it + 2, nstg);
        }
        uint32_t base = S_base + (uint32_t)(stg * STAGE * 2);

#pragma unroll
        for (int ks = 0; ks < 2; ks++) {
            uint32_t af[4][4], bf[4][2];
#pragma unroll
            for (int mt = 0; mt < 4; mt++) {
                asm volatile(
                    "ldmatrix.sync.aligned.m8n8.x4.shared.b16 {%0,%1,%2,%3}, [%4];"
                    : "=r"(af[mt][0]), "=r"(af[mt][1]), "=r"(af[mt][2]), "=r"(af[mt][3])
                    : "r"(base + a_off[mt] + ks * 32));
            }
#pragma unroll
            for (int p = 0; p < 2; p++) {
                asm volatile(
                    "ldmatrix.sync.aligned.m8n8.x4.shared.b16 {%0,%1,%2,%3}, [%4];"
                    : "=r"(bf[2 * p][0]), "=r"(bf[2 * p][1]),
                      "=r"(bf[2 * p + 1][0]), "=r"(bf[2 * p + 1][1])
                    : "r"(base + b_off[p] + ks * 32));
            }
#pragma unroll
            for (int mt = 0; mt < 4; mt++)
#pragma unroll
                for (int nt = 0; nt < 4; nt++)
                    asm volatile(
                        "mma.sync.aligned.m16n8k16.row.col.f32.f16.f16.f32 "
                        "{%0,%1,%2,%3}, {%4,%5,%6,%7}, {%8,%9}, {%0,%1,%2,%3};"
                        : "+f"(acc[mt][nt][0]), "+f"(acc[mt][nt][1]),
                          "+f"(acc[mt][nt][2]), "+f"(acc[mt][nt][3])
                        : "r"(af[mt][0]), "r"(af[mt][1]), "r"(af[mt][2]), "r"(af[mt][3]),
                          "r"(bf[nt][0]), "r"(bf[nt][1]));
        }
        __syncthreads();
        if (++stg == 3) stg = 0;
    }

    // epilogue
#pragma unroll
    for (int mt = 0; mt < 4; mt++) {
#pragma unroll
        for (int half_i = 0; half_i < 2; half_i++) {
            int row = block_m + wm * 64 + mt * 16 + lr + half_i * 8;
            if (row >= M) continue;
#pragma unroll
            for (int nt = 0; nt < 4; nt++) {
                int gc = block_n + wn * 32 + nt * 8 + 2 * lc;
                float v0 = acc[mt][nt][half_i * 2 + 0] + bias[gc];
                float v1 = acc[mt][nt][half_i * 2 + 1] + bias[gc + 1];
                if (RELU) { v0 = fmaxf(v0, 0.0f); v1 = fmaxf(v1, 0.0f); }
                if (OUTHALF) {
                    __half2 h = __float22half2_rn(make_float2(v0, v1));
                    *(__half2*)((__half*)Cv + (size_t)row * N + gc) = h;
                } else {
                    *(float2*)((float*)Cv + (size_t)row * N + gc) = make_float2(v0, v1);
                }
            }
        }
    }
}

constexpr size_t smem_h3(int WMW, int WNW) {
    return (size_t)(3 * ((WMW * 64) * 40 + (WNW * 32) * 40)) * 2;   // 76800
}

// ---------------- TF32 GEMM (G4 only) ----------------------------------------
template <int WMW, int WNW, int TPB, bool RELU>
__global__ __launch_bounds__(TPB) void gemm_v2(
    int M, int N, int K,
    const float* __restrict__ A, const float* __restrict__ B,
    const float* __restrict__ bias,
    const float* __restrict__ D, const float* __restrict__ rowscale,
    float* __restrict__ C)
{
    constexpr int BM = WMW * 64, BN = WNW * 32, BK = 32;
    constexpr int AST = BK + 4;
    constexpr int BST = BN + 8;
    constexpr int ATILE = BM * AST;
    constexpr int BTILE = BK * BST;
    constexpr int CA = BM * BK / (4 * TPB);
    constexpr int CB = BK * BN / (4 * TPB);
    static_assert(CA >= 1 && CB >= 1, "tile/thread mismatch");
    static_assert(WMW * WNW * 32 == TPB, "warp layout mismatch");

    extern __shared__ float smem[];
    float* AsB = smem;
    float* BsB = smem + 2 * ATILE;

    int tid = threadIdx.x;
    int warp = tid >> 5, lane = tid & 31;
    int wm = warp / WNW, wn = warp % WNW;
    int lr = lane >> 2, lc = lane & 3;
    int block_m = blockIdx.y * BM, block_n = blockIdx.x * BN;

    float acc[4][4][4];
#pragma unroll
    for (int a = 0; a < 4; a++)
#pragma unroll
        for (int b = 0; b < 4; b++)
#pragma unroll
            for (int c = 0; c < 4; c++) acc[a][b][c] = 0.0f;

    auto load_tiles = [&](int it, float* As, float* Bs) {
#pragma unroll
        for (int i = 0; i < CA; i++) {
            int f = tid + TPB * i;
            int m = f >> 3, q = f & 7;
            int gr = block_m + m;
            uint32_t dst = (uint32_t)__cvta_generic_to_shared(As + m * AST + 4 * q);
            const float* src = A + (size_t)gr * K + it * BK + 4 * q;
            int sz = (gr < M) ? 16 : 0;
            asm volatile("cp.async.cg.shared.global [%0], [%1], 16, %2;"
                         :: "r"(dst), "l"(src), "r"(sz));
        }
#pragma unroll
        for (int i = 0; i < CB; i++) {
            int f = tid + TPB * i;
            int n4 = f % (BN / 4), k = f / (BN / 4);
            uint32_t dst = (uint32_t)__cvta_generic_to_shared(Bs + k * BST + 4 * n4);
            const float* src = B + (size_t)(it * BK + k) * N + block_n + 4 * n4;
            asm volatile("cp.async.cg.shared.global [%0], [%1], 16;"
                         :: "r"(dst), "l"(src));
        }
        asm volatile("cp.async.commit_group;");
    };

    int nIter = K / BK;
    load_tiles(0, AsB, BsB);

    for (int it = 0; it < nIter; ++it) {
        int buf = it & 1;
        if (it + 1 < nIter) {
            load_tiles(it + 1, AsB + (buf ^ 1) * ATILE, BsB + (buf ^ 1) * BTILE);
            asm volatile("cp.async.wait_group 1;");
        } else {
            asm volatile("cp.async.wait_group 0;");
        }
        __syncthreads();
        const float* As = AsB + buf * ATILE;
        const float* Bs = BsB + buf * BTILE;

#pragma unroll
        for (int ks = 0; ks < 4; ks++) {
            int col = ks * 8 + lc;
            uint32_t af[4][4], bfr[4][2];
#pragma unroll
            for (int mt = 0; mt < 4; mt++) {
                const float* ap = As + (wm * 64 + mt * 16 + lr) * AST + col;
                af[mt][0] = tf32u(ap[0]);
                af[mt][1] = tf32u(ap[8 * AST]);
                af[mt][2] = tf32u(ap[4]);
                af[mt][3] = tf32u(ap[8 * AST + 4]);
            }
#pragma unroll
            for (int nt = 0; nt < 4; nt++) {
                const float* bp = Bs + col * BST + wn * 32 + nt * 8 + lr;
                bfr[nt][0] = __float_as_uint(bp[0]);
                bfr[nt][1] = __float_as_uint(bp[4 * BST]);
            }
#pragma unroll
            for (int mt = 0; mt < 4; mt++)
#pragma unroll
                for (int nt = 0; nt < 4; nt++)
                    asm volatile(
                        "mma.sync.aligned.m16n8k8.row.col.f32.tf32.tf32.f32 "
                        "{%0,%1,%2,%3}, {%4,%5,%6,%7}, {%8,%9}, {%0,%1,%2,%3};"
                        : "+f"(acc[mt][nt][0]), "+f"(acc[mt][nt][1]),
                          "+f"(acc[mt][nt][2]), "+f"(acc[mt][nt][3])
                        : "r"(af[mt][0]), "r"(af[mt][1]), "r"(af[mt][2]), "r"(af[mt][3]),
                          "r"(bfr[nt][0]), "r"(bfr[nt][1]));
        }
        __syncthreads();
    }

#pragma unroll
    for (int mt = 0; mt < 4; mt++) {
#pragma unroll
        for (int half_i = 0; half_i < 2; half_i++) {
            int row = block_m + wm * 64 + mt * 16 + lr + half_i * 8;
            if (row >= M) continue;
            float rs = rowscale[row];
#pragma unroll
            for (int nt = 0; nt < 4; nt++) {
                int gc = block_n + wn * 32 + nt * 8 + 2 * lc;
                float v0 = acc[mt][nt][half_i * 2 + 0];
                float v1 = acc[mt][nt][half_i * 2 + 1];
                float2 d = *(const float2*)(D + (size_t)row * N + gc);
                v0 += d.x; v1 += d.y;
                v0 = rs * v0 + bias[gc];
                v1 = rs * v1 + bias[gc + 1];
                if (RELU) { v0 = fmaxf(v0, 0.0f); v1 = fmaxf(v1, 0.0f); }
                *(float2*)(C + (size_t)row * N + gc) = make_float2(v0, v1);
            }
        }
    }
}

constexpr size_t smem_bytes(int WMW, int WNW) {
    return (size_t)(2 * (WMW * 64) * 36 + 2 * 32 * (WNW * 32 + 8)) * 4;
}

// ---------------- edge kernel (c1 atomics + relu_s fp16 store) ---------------
__device__ __forceinline__ void red4(float* p, float4 v) {
    asm volatile("red.global.add.v4.f32 [%0], {%1,%2,%3,%4};"
                 :: "l"(p), "f"(v.x), "f"(v.y), "f"(v.z), "f"(v.w) : "memory");
}
__device__ __forceinline__ float2 h2f(uint32_t u) {
    return __half22float2(*(__half2*)&u);
}
__device__ __forceinline__ uint32_t f2h(float a, float b) {
    __half2 h = __float22half2_rn(make_float2(a, b));
    return *(uint32_t*)&h;
}

__global__ __launch_bounds__(256) void edge_kernel(const int* __restrict__ en) {
    int wg = (blockIdx.x * blockDim.x + threadIdx.x) >> 5;
    int lane = threadIdx.x & 31;
    if (wg >= NEDGE) return;
    int v0 = en[wg * 3 + 0];
    int v1 = en[wg * 3 + 1];
    int v2 = en[wg * 3 + 2];
    float d0 = g_dscale[v0], d1 = g_dscale[v1], d2 = g_dscale[v2];

    if (lane < 16) {
        float4 a = *(const float4*)(g_emb_new + (size_t)v0 * RANK + lane * 4);
        float4 b = *(const float4*)(g_emb_new + (size_t)v1 * RANK + lane * 4);
        float4 c = *(const float4*)(g_emb_new + (size_t)v2 * RANK + lane * 4);
        a.x *= d0; a.y *= d0; a.z *= d0; a.w *= d0;
        b.x *= d1; b.y *= d1; b.z *= d1; b.w *= d1;
        c.x *= d2; c.y *= d2; c.z *= d2; c.w *= d2;
        float h0 = 0.5f * d0, h1 = 0.5f * d1, h2 = 0.5f * d2;
        float4 o0 = make_float4(h0 * b.x * c.x, h0 * b.y * c.y, h0 * b.z * c.z, h0 * b.w * c.w);
        float4 o1 = make_float4(h1 * a.x * c.x, h1 * a.y * c.y, h1 * a.z * c.z, h1 * a.w * c.w);
        float4 o2 = make_float4(h2 * a.x * b.x, h2 * a.y * b.y, h2 * a.z * b.z, h2 * a.w * b.w);
        red4(g_sum_c1 + (size_t)v0 * RANK + lane * 4, o0);
        red4(g_sum_c1 + (size_t)v1 * RANK + lane * 4, o1);
        red4(g_sum_c1 + (size_t)v2 * RANK + lane * 4, o2);
    }

    const uint4* e0 = (const uint4*)(g_emb2_h + (size_t)v0 * OUTD);
    const uint4* e1 = (const uint4*)(g_emb2_h + (size_t)v1 * OUTD);
    const uint4* e2 = (const uint4*)(g_emb2_h + (size_t)v2 * OUTD);
    uint4 x = e0[lane], y = e1[lane], z = e2[lane];
    uint4 o;
    {
        float2 fx, fy, fz;
        fx = h2f(x.x); fy = h2f(y.x); fz = h2f(z.x);
        o.x = f2h(fmaxf(fx.x + fy.x + fz.x, 0.0f), fmaxf(fx.y + fy.y + fz.y, 0.0f));
        fx = h2f(x.y); fy = h2f(y.y); fz = h2f(z.y);
        o.y = f2h(fmaxf(fx.x + fy.x + fz.x, 0.0f), fmaxf(fx.y + fy.y + fz.y, 0.0f));
        fx = h2f(x.z); fy = h2f(y.z); fz = h2f(z.z);
        o.z = f2h(fmaxf(fx.x + fy.x + fz.x, 0.0f), fmaxf(fx.y + fy.y + fz.y, 0.0f));
        fx = h2f(x.w); fy = h2f(y.w); fz = h2f(z.w);
        o.w = f2h(fmaxf(fx.x + fy.x + fz.x, 0.0f), fmaxf(fx.y + fy.y + fz.y, 0.0f));
    }
    ((uint4*)(g_relu_s + (size_t)wg * OUTD))[lane] = o;
}

// ---------------- node gather: sum_s[v] = sum over incident edges ------------
__global__ __launch_bounds__(256) void gather_kernel() {
    int v = (blockIdx.x * blockDim.x + threadIdx.x) >> 5;
    int lane = threadIdx.x & 31;
    if (v >= N_NODES) return;
    int d = g_deg[v];
    if (d > CSRCAP) d = CSRCAP;
    float a[8];
#pragma unroll
    for (int q = 0; q < 8; q++) a[q] = 0.0f;
    for (int t = 0; t < d; t++) {
        int e = g_csr[v * CSRCAP + t];
        uint4 pk = ((const uint4*)(g_relu_s + (size_t)e * OUTD))[lane];
        float2 f0 = h2f(pk.x), f1 = h2f(pk.y), f2 = h2f(pk.z), f3 = h2f(pk.w);
        a[0] += f0.x; a[1] += f0.y; a[2] += f1.x; a[3] += f1.y;
        a[4] += f2.x; a[5] += f2.y; a[6] += f3.x; a[7] += f3.y;
    }
    float4* o = (float4*)(g_sum_s + (size_t)v * OUTD);
    o[lane * 2]     = make_float4(a[0], a[1], a[2], a[3]);
    o[lane * 2 + 1] = make_float4(a[4], a[5], a[6], a[7]);
}

// ---------------- launch ----------------------------------------------------
extern "C" void kernel_launch(void* const* d_in, const int* in_sizes, int n_in,
                              void* d_out, int out_size) {
    const float* emb = (const float*)d_in[0];
    const int*   en  = (const int*)d_in[1];
    const float* Wp  = (const float*)d_in[2];
    const float* bp  = (const float*)d_in[3];
    const float* W2a = (const float*)d_in[4];
    const float* b2a = (const float*)d_in[5];
    const float* W2b = (const float*)d_in[6];
    const float* b2b = (const float*)d_in[7];
    const float* Wq  = (const float*)d_in[8];
    const float* bq  = (const float*)d_in[9];
    float* out = (float*)d_out;

    float *p_emb_new, *p_sum_c1, *p_sum_s, *p_invdeg, *p_wq_r, *p_bias1, *p_bias2;
    __half *p_emb_h, *p_hid_h, *p_emb2_h, *p_wp_h, *p_w2a_h, *p_w2b_h;
    cudaGetSymbolAddress((void**)&p_emb_new, g_emb_new);
    cudaGetSymbolAddress((void**)&p_sum_c1,  g_sum_c1);
    cudaGetSymbolAddress((void**)&p_sum_s,   g_sum_s);
    cudaGetSymbolAddress((void**)&p_invdeg,  g_invdeg);
    cudaGetSymbolAddress((void**)&p_wq_r,    g_wq_r);
    cudaGetSymbolAddress((void**)&p_bias1,   g_bias1);
    cudaGetSymbolAddress((void**)&p_bias2,   g_bias2);
    cudaGetSymbolAddress((void**)&p_emb_h,   g_emb_h);
    cudaGetSymbolAddress((void**)&p_hid_h,   g_hid_h);
    cudaGetSymbolAddress((void**)&p_emb2_h,  g_emb2_h);
    cudaGetSymbolAddress((void**)&p_wp_h,    g_wp_h);
    cudaGetSymbolAddress((void**)&p_w2a_h,   g_w2a_h);
    cudaGetSymbolAddress((void**)&p_w2b_h,   g_w2b_h);

    constexpr size_t SH18 = smem_h3(1, 8);    // 76800
    constexpr size_t SH42 = smem_h3(4, 2);    // 76800
    constexpr size_t SM18 = smem_bytes(1, 8); // 86016
    cudaFuncSetAttribute(gemm_h<1,8,256,true, true >, cudaFuncAttributeMaxDynamicSharedMemorySize, (int)SH18);
    cudaFuncSetAttribute(gemm_h<1,8,256,false,true >, cudaFuncAttributeMaxDynamicSharedMemorySize, (int)SH18);
    cudaFuncSetAttribute(gemm_h<4,2,256,false,false>, cudaFuncAttributeMaxDynamicSharedMemorySize, (int)SH42);
    cudaFuncSetAttribute(gemm_v2<1,8,256,true>,       cudaFuncAttributeMaxDynamicSharedMemorySize, (int)SM18);

    const int M = N_NODES;

    // 1..3: prep  (slot 4 = G2 for the ncu window)
    {
        int total = FEAT * RANK + FEAT * HIDD + HIDD * OUTD + RANK * OUTD + RANK + HIDD;
        wprep_kernel<<<(total + 255) / 256, 256>>>(Wp, bp, W2a, b2a, W2b, Wq);  // 1
    }
    {
        int n4 = N_NODES * FEAT / 4;
        emb_half_kernel<<<(n4 + 255) / 256, 256>>>((const float4*)emb, n4);     // 2
    }
    zero_kernel<<<1024, 256>>>();                                               // 3

    // 4: G2: hid = relu(emb @ W2a + bias2) -> half   [64x256]
    gemm_h<1,8,256,true,true><<<dim3(HIDD / 256, (M + 63) / 64), 256, SH18>>>(
        M, HIDD, FEAT, p_emb_h, p_w2a_h, p_bias2, p_hid_h);
    // 5: G1: emb_new = emb @ Wp + bias1 -> float     [256x64]
    gemm_h<4,2,256,false,false><<<dim3(1, (M + 255) / 256), 256, SH42>>>(
        M, RANK, FEAT, p_emb_h, p_wp_h, p_bias1, p_emb_new);
    // 6: G3: emb2 = hid @ W2b + b2b -> half          [64x256]
    gemm_h<1,8,256,false,true><<<dim3(1, (M + 63) / 64), 256, SH18>>>(
        M, OUTD, HIDD, p_hid_h, p_w2b_h, b2b, p_emb2_h);
    // 7: CSR build (+degree)
    csr_kernel<<<(NEDGE * KE + 255) / 256, 256>>>(en);
    // 8: degree-derived scales
    scale_kernel<<<(N_NODES + 255) / 256, 256>>>();
    // 9: edge kernel: c1 atomics + relu_s fp16 store
    edge_kernel<<<(NEDGE * 32) / 256, 256>>>(en);
    // 10: node gather: sum_s
    gather_kernel<<<(N_NODES * 32 + 255) / 256, 256>>>();
    // 11: G4: out = relu(invdeg * (sum_c1 @ Wq + sum_s) + bq)  [tf32, CVTA]
    gemm_v2<1,8,256,true><<<dim3(1, (M + 63) / 64), 256, SM18>>>(
        M, OUTD, RANK, p_sum_c1, p_wq_r, bq, p_sum_s, p_invdeg, out);
}

// round 17
// speedup vs baseline: 1.4182x; 1.0277x over previous
#include <cuda_runtime.h>
#include <cuda_fp16.h>
#include <math.h>
#include <stdint.h>

#define N_NODES 100000
#define FEAT    256
#define RANK    64
#define HIDD    512
#define OUTD    256
#define NEDGE   200000
#define KE      3
#define CSRCAP  12

// ---------------- scratch (device globals; no allocations allowed) ----------
__device__ __align__(16) float  g_emb_new[N_NODES * RANK];
__device__ __align__(16) __half g_hid_h[(size_t)N_NODES * HIDD];
__device__ __align__(16) __half g_emb2_h[(size_t)N_NODES * OUTD];
__device__ __align__(16) float  g_sum_c1[N_NODES * RANK];
__device__ __align__(16) float  g_sum_s[N_NODES * OUTD];
__device__ __align__(16) __half g_emb_h[(size_t)N_NODES * FEAT];
__device__ __align__(16) __half g_wp_h[RANK * FEAT];                 // [N][K]
__device__ __align__(16) __half g_w2a_h[HIDD * FEAT];
__device__ __align__(16) __half g_w2b_h[OUTD * HIDD];
__device__ __align__(16) float  g_wq_r[RANK * OUTD];                 // tf32 [K][N]
__device__ __align__(16) float  g_bias1[RANK];
__device__ __align__(16) float  g_bias2[HIDD];
__device__ int   g_csr[N_NODES * CSRCAP];
__device__ int   g_deg[N_NODES];
__device__ float g_dscale[N_NODES];
__device__ float g_invdeg[N_NODES];

__device__ __forceinline__ float tf32r(float x) {
    uint32_t r;
    asm("cvt.rna.tf32.f32 %0, %1;" : "=r"(r) : "f"(x));
    return __uint_as_float(r);
}
__device__ __forceinline__ uint32_t tf32u(float x) {
    uint32_t r;
    asm("cvt.rna.tf32.f32 %0, %1;" : "=r"(r) : "f"(x));
    return r;
}
__device__ __forceinline__ float2 h2f(uint32_t u) {
    return __half22float2(*(__half2*)&u);
}

// ---------------- utility kernels -------------------------------------------
__global__ void zero_deg_kernel() {
    int i = blockIdx.x * blockDim.x + threadIdx.x;
    if (i < N_NODES) g_deg[i] = 0;
}

__global__ void csr_kernel(const int* __restrict__ en) {
    int i = blockIdx.x * blockDim.x + threadIdx.x;
    if (i < NEDGE * KE) {
        int v = en[i];
        int pos = atomicAdd(&g_deg[v], 1);
        if (pos < CSRCAP) g_csr[v * CSRCAP + pos] = i / KE;
    }
}

__global__ void scale_kernel() {
    int v = blockIdx.x * blockDim.x + threadIdx.x;
    if (v < N_NODES) {
        float d = (float)g_deg[v];
        g_dscale[v] = cbrtf(d);
        g_invdeg[v] = 1.0f / d;
    }
}

__global__ void emb_half_kernel(const float4* __restrict__ src, int n4) {
    int i = blockIdx.x * blockDim.x + threadIdx.x;
    if (i < n4) {
        float4 v = src[i];
        __half2 h0 = __float22half2_rn(make_float2(v.x, v.y));
        __half2 h1 = __float22half2_rn(make_float2(v.z, v.w));
        uint2 pk;
        pk.x = *(uint32_t*)&h0;
        pk.y = *(uint32_t*)&h1;
        ((uint2*)g_emb_h)[i] = pk;
    }
}

__global__ void wprep_kernel(const float* __restrict__ Wp,  const float* __restrict__ bp,
                             const float* __restrict__ W2a, const float* __restrict__ b2a,
                             const float* __restrict__ W2b,
                             const float* __restrict__ Wq) {
    const int S1 = FEAT * RANK;
    const int S2 = S1 + FEAT * HIDD;
    const int S3 = S2 + HIDD * OUTD;
    const int S4 = S3 + RANK * OUTD;
    const int S5 = S4 + RANK;
    const int S6 = S5 + HIDD;
    int i = blockIdx.x * blockDim.x + threadIdx.x;
    if (i < S1) {
        int k = i / RANK, n = i % RANK;
        g_wp_h[n * FEAT + k] = __float2half_rn(Wp[i]);
    } else if (i < S2) {
        int j = i - S1;
        int k = j / HIDD, n = j % HIDD;
        g_w2a_h[n * FEAT + k] = __float2half_rn(W2a[j]);
    } else if (i < S3) {
        int j = i - S2;
        int k = j / OUTD, n = j % OUTD;
        g_w2b_h[n * HIDD + k] = __float2half_rn(W2b[j]);
    } else if (i < S4) {
        int j = i - S3;
        g_wq_r[j] = tf32r(Wq[j]);
    } else if (i < S5) {
        int j = i - S4;
        g_bias1[j] = Wp[FEAT * RANK + j] + bp[j];
    } else if (i < S6) {
        int j = i - S5;
        g_bias2[j] = W2a[FEAT * HIDD + j] + b2a[j];
    }
}

// ---------------- fp16 GEMM: ldmatrix + 3-stage ring, one sync/iter ----------
template <int WMW, int WNW, int TPB, bool RELU, bool OUTHALF>
__global__ __launch_bounds__(TPB) void gemm_h(
    int M, int N, int K,
    const __half* __restrict__ A, const __half* __restrict__ Bt,
    const float* __restrict__ bias, void* __restrict__ Cv)
{
    constexpr int BM = WMW * 64, BN = WNW * 32, BK = 32;
    constexpr int AST = 40;
    constexpr int BST = 40;
    constexpr int ATILE = BM * AST;
    constexpr int BTILE = BN * BST;
    constexpr int STAGE = ATILE + BTILE;
    constexpr int CA = BM * 4 / TPB;
    constexpr int CB = BN * 4 / TPB;
    static_assert(CA >= 1 && CB >= 1, "tile/thread mismatch");
    static_assert(WMW * WNW * 32 == TPB, "warp layout mismatch");

    extern __shared__ __half smemh[];

    int tid = threadIdx.x;
    int warp = tid >> 5, lane = tid & 31;
    int wm = warp / WNW, wn = warp % WNW;
    int lr = lane >> 2, lc = lane & 3;
    int block_m = blockIdx.y * BM, block_n = blockIdx.x * BN;

    int lid8 = lane & 7;
    int jrow = (lane >> 3) & 1;
    int jcol = lane >> 4;

    uint32_t S_base = (uint32_t)__cvta_generic_to_shared(smemh);

    uint32_t a_off[4], b_off[2];
#pragma unroll
    for (int mt = 0; mt < 4; mt++)
        a_off[mt] = (uint32_t)(((wm * 64 + mt * 16 + jrow * 8 + lid8) * AST + jcol * 8) * 2);
#pragma unroll
    for (int p = 0; p < 2; p++)
        b_off[p] = (uint32_t)((ATILE + (wn * 32 + p * 16 + jcol * 8 + lid8) * BST + jrow * 8) * 2);

    float acc[4][4][4];
#pragma unroll
    for (int a = 0; a < 4; a++)
#pragma unroll
        for (int b = 0; b < 4; b++)
#pragma unroll
            for (int c = 0; c < 4; c++) acc[a][b][c] = 0.0f;

    auto load_tiles = [&](int it, int stg) {
        __half* As = smemh + stg * STAGE;
        __half* Bs = As + ATILE;
#pragma unroll
        for (int i = 0; i < CA; i++) {
            int f = tid + TPB * i;
            int m = f >> 2, q = f & 3;
            int gr = block_m + m;
            uint32_t dst = (uint32_t)__cvta_generic_to_shared(As + m * AST + 8 * q);
            const __half* src = A + (size_t)gr * K + it * BK + 8 * q;
            int sz = (gr < M) ? 16 : 0;
            asm volatile("cp.async.cg.shared.global [%0], [%1], 16, %2;"
                         :: "r"(dst), "l"(src), "r"(sz));
        }
#pragma unroll
        for (int i = 0; i < CB; i++) {
            int f = tid + TPB * i;
            int n = f >> 2, q = f & 3;
            uint32_t dst = (uint32_t)__cvta_generic_to_shared(Bs + n * BST + 8 * q);
            const __half* src = Bt + (size_t)(block_n + n) * K + it * BK + 8 * q;
            asm volatile("cp.async.cg.shared.global [%0], [%1], 16;"
                         :: "r"(dst), "l"(src));
        }
        asm volatile("cp.async.commit_group;");
    };

    int nIter = K / BK;
    load_tiles(0, 0);
    if (nIter > 1) load_tiles(1, 1);

    int stg = 0;
    for (int it = 0; it < nIter; ++it) {
        if (it + 1 < nIter) asm volatile("cp.async.wait_group 1;");
        else                asm volatile("cp.async.wait_group 0;");
        __syncthreads();   // single barrier per iter: also retires last-iter readers
        if (it + 2 < nIter) {
            int nstg = stg + 2; if (nstg >= 3) nstg -= 3;
            load_tiles(it + 2, nstg);
        }
        uint32_t base = S_base + (uint32_t)(stg * STAGE * 2);

#pragma unroll
        for (int ks = 0; ks < 2; ks++) {
            uint32_t af[4][4], bf[4][2];
#pragma unroll
            for (int mt = 0; mt < 4; mt++) {
                asm volatile(
                    "ldmatrix.sync.aligned.m8n8.x4.shared.b16 {%0,%1,%2,%3}, [%4];"
                    : "=r"(af[mt][0]), "=r"(af[mt][1]), "=r"(af[mt][2]), "=r"(af[mt][3])
                    : "r"(base + a_off[mt] + ks * 32));
            }
#pragma unroll
            for (int p = 0; p < 2; p++) {
                asm volatile(
                    "ldmatrix.sync.aligned.m8n8.x4.shared.b16 {%0,%1,%2,%3}, [%4];"
                    : "=r"(bf[2 * p][0]), "=r"(bf[2 * p][1]),
                      "=r"(bf[2 * p + 1][0]), "=r"(bf[2 * p + 1][1])
                    : "r"(base + b_off[p] + ks * 32));
            }
#pragma unroll
            for (int mt = 0; mt < 4; mt++)
#pragma unroll
                for (int nt = 0; nt < 4; nt++)
                    asm volatile(
                        "mma.sync.aligned.m16n8k16.row.col.f32.f16.f16.f32 "
                        "{%0,%1,%2,%3}, {%4,%5,%6,%7}, {%8,%9}, {%0,%1,%2,%3};"
                        : "+f"(acc[mt][nt][0]), "+f"(acc[mt][nt][1]),
                          "+f"(acc[mt][nt][2]), "+f"(acc[mt][nt][3])
                        : "r"(af[mt][0]), "r"(af[mt][1]), "r"(af[mt][2]), "r"(af[mt][3]),
                          "r"(bf[nt][0]), "r"(bf[nt][1]));
        }
        if (++stg == 3) stg = 0;
    }

    // epilogue
#pragma unroll
    for (int mt = 0; mt < 4; mt++) {
#pragma unroll
        for (int half_i = 0; half_i < 2; half_i++) {
            int row = block_m + wm * 64 + mt * 16 + lr + half_i * 8;
            if (row >= M) continue;
#pragma unroll
            for (int nt = 0; nt < 4; nt++) {
                int gc = block_n + wn * 32 + nt * 8 + 2 * lc;
                float v0 = acc[mt][nt][half_i * 2 + 0] + bias[gc];
                float v1 = acc[mt][nt][half_i * 2 + 1] + bias[gc + 1];
                if (RELU) { v0 = fmaxf(v0, 0.0f); v1 = fmaxf(v1, 0.0f); }
                if (OUTHALF) {
                    __half2 h = __float22half2_rn(make_float2(v0, v1));
                    *(__half2*)((__half*)Cv + (size_t)row * N + gc) = h;
                } else {
                    *(float2*)((float*)Cv + (size_t)row * N + gc) = make_float2(v0, v1);
                }
            }
        }
    }
}

constexpr size_t smem_h3(int WMW, int WNW) {
    return (size_t)(3 * ((WMW * 64) * 40 + (WNW * 32) * 40)) * 2;
}

// ---------------- TF32 GEMM (G4 only) ----------------------------------------
template <int WMW, int WNW, int TPB, bool RELU>
__global__ __launch_bounds__(TPB) void gemm_v2(
    int M, int N, int K,
    const float* __restrict__ A, const float* __restrict__ B,
    const float* __restrict__ bias,
    const float* __restrict__ D, const float* __restrict__ rowscale,
    float* __restrict__ C)
{
    constexpr int BM = WMW * 64, BN = WNW * 32, BK = 32;
    constexpr int AST = BK + 4;
    constexpr int BST = BN + 8;
    constexpr int ATILE = BM * AST;
    constexpr int BTILE = BK * BST;
    constexpr int CA = BM * BK / (4 * TPB);
    constexpr int CB = BK * BN / (4 * TPB);
    static_assert(CA >= 1 && CB >= 1, "tile/thread mismatch");
    static_assert(WMW * WNW * 32 == TPB, "warp layout mismatch");

    extern __shared__ float smem[];
    float* AsB = smem;
    float* BsB = smem + 2 * ATILE;

    int tid = threadIdx.x;
    int warp = tid >> 5, lane = tid & 31;
    int wm = warp / WNW, wn = warp % WNW;
    int lr = lane >> 2, lc = lane & 3;
    int block_m = blockIdx.y * BM, block_n = blockIdx.x * BN;

    float acc[4][4][4];
#pragma unroll
    for (int a = 0; a < 4; a++)
#pragma unroll
        for (int b = 0; b < 4; b++)
#pragma unroll
            for (int c = 0; c < 4; c++) acc[a][b][c] = 0.0f;

    auto load_tiles = [&](int it, float* As, float* Bs) {
#pragma unroll
        for (int i = 0; i < CA; i++) {
            int f = tid + TPB * i;
            int m = f >> 3, q = f & 7;
            int gr = block_m + m;
            uint32_t dst = (uint32_t)__cvta_generic_to_shared(As + m * AST + 4 * q);
            const float* src = A + (size_t)gr * K + it * BK + 4 * q;
            int sz = (gr < M) ? 16 : 0;
            asm volatile("cp.async.cg.shared.global [%0], [%1], 16, %2;"
                         :: "r"(dst), "l"(src), "r"(sz));
        }
#pragma unroll
        for (int i = 0; i < CB; i++) {
            int f = tid + TPB * i;
            int n4 = f % (BN / 4), k = f / (BN / 4);
            uint32_t dst = (uint32_t)__cvta_generic_to_shared(Bs + k * BST + 4 * n4);
            const float* src = B + (size_t)(it * BK + k) * N + block_n + 4 * n4;
            asm volatile("cp.async.cg.shared.global [%0], [%1], 16;"
                         :: "r"(dst), "l"(src));
        }
        asm volatile("cp.async.commit_group;");
    };

    int nIter = K / BK;
    load_tiles(0, AsB, BsB);

    for (int it = 0; it < nIter; ++it) {
        int buf = it & 1;
        if (it + 1 < nIter) {
            load_tiles(it + 1, AsB + (buf ^ 1) * ATILE, BsB + (buf ^ 1) * BTILE);
            asm volatile("cp.async.wait_group 1;");
        } else {
            asm volatile("cp.async.wait_group 0;");
        }
        __syncthreads();
        const float* As = AsB + buf * ATILE;
        const float* Bs = BsB + buf * BTILE;

#pragma unroll
        for (int ks = 0; ks < 4; ks++) {
            int col = ks * 8 + lc;
            uint32_t af[4][4], bfr[4][2];
#pragma unroll
            for (int mt = 0; mt < 4; mt++) {
                const float* ap = As + (wm * 64 + mt * 16 + lr) * AST + col;
                af[mt][0] = tf32u(ap[0]);
                af[mt][1] = tf32u(ap[8 * AST]);
                af[mt][2] = tf32u(ap[4]);
                af[mt][3] = tf32u(ap[8 * AST + 4]);
            }
#pragma unroll
            for (int nt = 0; nt < 4; nt++) {
                const float* bp = Bs + col * BST + wn * 32 + nt * 8 + lr;
                bfr[nt][0] = __float_as_uint(bp[0]);
                bfr[nt][1] = __float_as_uint(bp[4 * BST]);
            }
#pragma unroll
            for (int mt = 0; mt < 4; mt++)
#pragma unroll
                for (int nt = 0; nt < 4; nt++)
                    asm volatile(
                        "mma.sync.aligned.m16n8k8.row.col.f32.tf32.tf32.f32 "
                        "{%0,%1,%2,%3}, {%4,%5,%6,%7}, {%8,%9}, {%0,%1,%2,%3};"
                        : "+f"(acc[mt][nt][0]), "+f"(acc[mt][nt][1]),
                          "+f"(acc[mt][nt][2]), "+f"(acc[mt][nt][3])
                        : "r"(af[mt][0]), "r"(af[mt][1]), "r"(af[mt][2]), "r"(af[mt][3]),
                          "r"(bfr[nt][0]), "r"(bfr[nt][1]));
        }
        __syncthreads();
    }

#pragma unroll
    for (int mt = 0; mt < 4; mt++) {
#pragma unroll
        for (int half_i = 0; half_i < 2; half_i++) {
            int row = block_m + wm * 64 + mt * 16 + lr + half_i * 8;
            if (row >= M) continue;
            float rs = rowscale[row];
#pragma unroll
            for (int nt = 0; nt < 4; nt++) {
                int gc = block_n + wn * 32 + nt * 8 + 2 * lc;
                float v0 = acc[mt][nt][half_i * 2 + 0];
                float v1 = acc[mt][nt][half_i * 2 + 1];
                float2 d = *(const float2*)(D + (size_t)row * N + gc);
                v0 += d.x; v1 += d.y;
                v0 = rs * v0 + bias[gc];
                v1 = rs * v1 + bias[gc + 1];
                if (RELU) { v0 = fmaxf(v0, 0.0f); v1 = fmaxf(v1, 0.0f); }
                *(float2*)(C + (size_t)row * N + gc) = make_float2(v0, v1);
            }
        }
    }
}

constexpr size_t smem_bytes(int WMW, int WNW) {
    return (size_t)(2 * (WMW * 64) * 36 + 2 * 32 * (WNW * 32 + 8)) * 4;
}

// ---------------- fused node kernel: sum_c1 + sum_s by gather ----------------
// warp per node v:
//   sum_s[v]  = sum_{e in csr[v]} relu(emb2[v]+emb2[u1]+emb2[u2])   (fp16 in, fp32 acc)
//   sum_c1[v] = 0.5*ds_v * sum_e ds_u1*ds_u2 * emb_new[u1]*emb_new[u2]
__global__ __launch_bounds__(256) void node_kernel(const int* __restrict__ en) {
    int v = (blockIdx.x * blockDim.x + threadIdx.x) >> 5;
    int lane = threadIdx.x & 31;
    if (v >= N_NODES) return;
    int d = g_deg[v];
    if (d > CSRCAP) d = CSRCAP;
    float ds_v = g_dscale[v];

    uint4 xv = ((const uint4*)(g_emb2_h + (size_t)v * OUTD))[lane];
    float2 x0 = h2f(xv.x), x1 = h2f(xv.y), x2 = h2f(xv.z), x3 = h2f(xv.w);

    float as[8];
#pragma unroll
    for (int q = 0; q < 8; q++) as[q] = 0.0f;
    float4 ac = make_float4(0.f, 0.f, 0.f, 0.f);

    for (int t = 0; t < d; t++) {
        int e = g_csr[v * CSRCAP + t];
        int a = en[3 * e], b = en[3 * e + 1], c = en[3 * e + 2];
        int u1, u2;
        if (a == v)      { u1 = b; u2 = c; }
        else if (b == v) { u1 = a; u2 = c; }
        else             { u1 = a; u2 = b; }

        // s part: relu(x_v + x_u1 + x_u2), 8 halves per lane
        uint4 y = ((const uint4*)(g_emb2_h + (size_t)u1 * OUTD))[lane];
        uint4 z = ((const uint4*)(g_emb2_h + (size_t)u2 * OUTD))[lane];
        float2 fy, fz;
        fy = h2f(y.x); fz = h2f(z.x);
        as[0] += fmaxf(x0.x + fy.x + fz.x, 0.0f);
        as[1] += fmaxf(x0.y + fy.y + fz.y, 0.0f);
        fy = h2f(y.y); fz = h2f(z.y);
        as[2] += fmaxf(x1.x + fy.x + fz.x, 0.0f);
        as[3] += fmaxf(x1.y + fy.y + fz.y, 0.0f);
        fy = h2f(y.z); fz = h2f(z.z);
        as[4] += fmaxf(x2.x + fy.x + fz.x, 0.0f);
        as[5] += fmaxf(x2.y + fy.y + fz.y, 0.0f);
        fy = h2f(y.w); fz = h2f(z.w);
        as[6] += fmaxf(x3.x + fy.x + fz.x, 0.0f);
        as[7] += fmaxf(x3.y + fy.y + fz.y, 0.0f);

        // c1 part (lanes 0..15: RANK=64 floats as float4)
        if (lane < 16) {
            float4 p = *(const float4*)(g_emb_new + (size_t)u1 * RANK + lane * 4);
            float4 q = *(const float4*)(g_emb_new + (size_t)u2 * RANK + lane * 4);
            float s12 = g_dscale[u1] * g_dscale[u2];
            ac.x += s12 * p.x * q.x;
            ac.y += s12 * p.y * q.y;
            ac.z += s12 * p.z * q.z;
            ac.w += s12 * p.w * q.w;
        }
    }

    if (lane < 16) {
        float h = 0.5f * ds_v;
        *(float4*)(g_sum_c1 + (size_t)v * RANK + lane * 4) =
            make_float4(h * ac.x, h * ac.y, h * ac.z, h * ac.w);
    }
    float4* o = (float4*)(g_sum_s + (size_t)v * OUTD);
    o[lane * 2]     = make_float4(as[0], as[1], as[2], as[3]);
    o[lane * 2 + 1] = make_float4(as[4], as[5], as[6], as[7]);
}

// ---------------- launch ----------------------------------------------------
extern "C" void kernel_launch(void* const* d_in, const int* in_sizes, int n_in,
                              void* d_out, int out_size) {
    const float* emb = (const float*)d_in[0];
    const int*   en  = (const int*)d_in[1];
    const float* Wp  = (const float*)d_in[2];
    const float* bp  = (const float*)d_in[3];
    const float* W2a = (const float*)d_in[4];
    const float* b2a = (const float*)d_in[5];
    const float* W2b = (const float*)d_in[6];
    const float* b2b = (const float*)d_in[7];
    const float* Wq  = (const float*)d_in[8];
    const float* bq  = (const float*)d_in[9];
    float* out = (float*)d_out;

    float *p_emb_new, *p_sum_c1, *p_sum_s, *p_invdeg, *p_wq_r, *p_bias1, *p_bias2;
    __half *p_emb_h, *p_hid_h, *p_emb2_h, *p_wp_h, *p_w2a_h, *p_w2b_h;
    cudaGetSymbolAddress((void**)&p_emb_new, g_emb_new);
    cudaGetSymbolAddress((void**)&p_sum_c1,  g_sum_c1);
    cudaGetSymbolAddress((void**)&p_sum_s,   g_sum_s);
    cudaGetSymbolAddress((void**)&p_invdeg,  g_invdeg);
    cudaGetSymbolAddress((void**)&p_wq_r,    g_wq_r);
    cudaGetSymbolAddress((void**)&p_bias1,   g_bias1);
    cudaGetSymbolAddress((void**)&p_bias2,   g_bias2);
    cudaGetSymbolAddress((void**)&p_emb_h,   g_emb_h);
    cudaGetSymbolAddress((void**)&p_hid_h,   g_hid_h);
    cudaGetSymbolAddress((void**)&p_emb2_h,  g_emb2_h);
    cudaGetSymbolAddress((void**)&p_wp_h,    g_wp_h);
    cudaGetSymbolAddress((void**)&p_w2a_h,   g_w2a_h);
    cudaGetSymbolAddress((void**)&p_w2b_h,   g_w2b_h);

    constexpr size_t SH18 = smem_h3(1, 8);
    constexpr size_t SH42 = smem_h3(4, 2);
    constexpr size_t SM18 = smem_bytes(1, 8);
    cudaFuncSetAttribute(gemm_h<1,8,256,true, true >, cudaFuncAttributeMaxDynamicSharedMemorySize, (int)SH18);
    cudaFuncSetAttribute(gemm_h<1,8,256,false,true >, cudaFuncAttributeMaxDynamicSharedMemorySize, (int)SH18);
    cudaFuncSetAttribute(gemm_h<4,2,256,false,false>, cudaFuncAttributeMaxDynamicSharedMemorySize, (int)SH42);
    cudaFuncSetAttribute(gemm_v2<1,8,256,true>,       cudaFuncAttributeMaxDynamicSharedMemorySize, (int)SM18);

    const int M = N_NODES;

    // 1..3: prep  (slot 4 = G2 for the ncu window)
    {
        int total = FEAT * RANK + FEAT * HIDD + HIDD * OUTD + RANK * OUTD + RANK + HIDD;
        wprep_kernel<<<(total + 255) / 256, 256>>>(Wp, bp, W2a, b2a, W2b, Wq);  // 1
    }
    {
        int n4 = N_NODES * FEAT / 4;
        emb_half_kernel<<<(n4 + 255) / 256, 256>>>((const float4*)emb, n4);     // 2
    }
    zero_deg_kernel<<<(N_NODES + 255) / 256, 256>>>();                          // 3

    // 4: G2: hid = relu(emb @ W2a + bias2) -> half   [64x256]
    gemm_h<1,8,256,true,true><<<dim3(HIDD / 256, (M + 63) / 64), 256, SH18>>>(
        M, HIDD, FEAT, p_emb_h, p_w2a_h, p_bias2, p_hid_h);
    // 5: G1: emb_new = emb @ Wp + bias1 -> float     [256x64]
    gemm_h<4,2,256,false,false><<<dim3(1, (M + 255) / 256), 256, SH42>>>(
        M, RANK, FEAT, p_emb_h, p_wp_h, p_bias1, p_emb_new);
    // 6: G3: emb2 = hid @ W2b + b2b -> half          [64x256]
    gemm_h<1,8,256,false,true><<<dim3(1, (M + 63) / 64), 256, SH18>>>(
        M, OUTD, HIDD, p_hid_h, p_w2b_h, b2b, p_emb2_h);
    // 7: CSR build (+degree)
    csr_kernel<<<(NEDGE * KE + 255) / 256, 256>>>(en);
    // 8: degree-derived scales
    scale_kernel<<<(N_NODES + 255) / 256, 256>>>();
    // 9: fused node gather (sum_c1 + sum_s) — no atomics, no edge buffer
    node_kernel<<<(N_NODES * 32 + 255) / 256, 256>>>(en);
    // 10: G4: out = relu(invdeg * (sum_c1 @ Wq + sum_s) + bq)  [tf32, CVTA]
    gemm_v2<1,8,256,true><<<dim3(1, (M + 63) / 64), 256, SM18>>>(
        M, OUTD, RANK, p_sum_c1, p_wq_r, bq, p_sum_s, p_invdeg, out);
}